// round 1
// baseline (speedup 1.0000x reference)
#include <cuda_runtime.h>
#include <cuda_bf16.h>
#include <cstdint>

#define NN 193536
#define BB 16
#define CC 9
#define KK 1000
#define BC 144            // BB*CC
#define MAXDET 100
#define SCORE_T 0.05f
#define IOU_T 0.5f

// ---------------- scratch (static device globals; no dynamic alloc) ----------------
__device__ float              g_scores[(size_t)BC * NN];       // ~111.5 MB, layout [(b*9+c)][n]
__device__ float              g_topval[BC * KK];
__device__ int                g_topidx[BC * KK];
__device__ float4             g_topbox[BC * KK];
__device__ unsigned long long g_mask[(size_t)BC * KK * 16];    // 18.4 MB suppression bitmatrix
__device__ float              g_val[BC * KK];                  // post-NMS score (0 for invalid)
__device__ float              g_cval[BC * KK];                 // compacted survivors (desc order)
__device__ int                g_cidx[BC * KK];
__device__ int                g_cnt[BC];

// ---------------- K1: sigmoid + transpose scores to class-major ----------------
__global__ __launch_bounds__(256) void score_kernel(const float* __restrict__ cls,
                                                    const float* __restrict__ obj) {
    int b = blockIdx.y;
    int n0 = blockIdx.x * 256;
    int tid = threadIdx.x;
    __shared__ float sh[256 * 9];
    const float* src = cls + ((size_t)b * NN + n0) * 9;
    for (int i = tid; i < 2304; i += 256) sh[i] = src[i];
    __syncthreads();
    int n = n0 + tid;
    float so = 1.0f / (1.0f + expf(-obj[(size_t)b * NN + n]));
#pragma unroll
    for (int c = 0; c < 9; c++) {
        float s = 1.0f / (1.0f + expf(-sh[tid * 9 + c]));
        g_scores[((size_t)(b * 9 + c)) * NN + n] = s * so;
    }
}

// ---------------- scan helper: find boundary bin from top, given `need` ----------------
__device__ __forceinline__ void scan_boundary(unsigned* hist, unsigned* gsum, int NG,
                                              int tid, int* sh_sel, int* sh_need, int* sh_take) {
    if (tid < NG) {
        unsigned t = 0;
        int base = tid * 32;
#pragma unroll 8
        for (int i = 0; i < 32; i++) t += hist[base + i];
        gsum[tid] = t;
    }
    __syncthreads();
    if (tid == 0) {
        int need = *sh_need;
        unsigned acc = 0;
        int g = NG - 1;
        for (; g >= 0; g--) {
            if (acc + gsum[g] >= (unsigned)need) break;
            acc += gsum[g];
        }
        if (g < 0) {
            *sh_take = 1;  // fewer than `need` candidates total
        } else {
            int bin = g * 32 + 31;
            for (;; bin--) {
                if (acc + hist[bin] >= (unsigned)need) break;
                acc += hist[bin];
            }
            *sh_sel = bin;
            *sh_need = need - (int)acc;
        }
    }
    __syncthreads();
}

__device__ __forceinline__ void hist_add(unsigned* hist, int bin) {
    // warp-aggregated atomic: scores cluster into few float-exponent bins
    unsigned m = __match_any_sync(__activemask(), bin);
    int leader = __ffs(m) - 1;
    if ((threadIdx.x & 31) == leader) atomicAdd(&hist[bin], __popc(m));
}

// ---------------- K2: per-(b,c) exact top-1000 (radix-select + bitonic) ----------------
__global__ __launch_bounds__(1024) void select_kernel() {
    int bc = blockIdx.x;
    int tid = threadIdx.x;
    const float* sc = g_scores + (size_t)bc * NN;

    __shared__ unsigned hist[4096];
    __shared__ unsigned gsum[128];
    __shared__ unsigned long long arr[2048];
    __shared__ int sh_sel, sh_need, sh_take, sh_cnt;

    // ---- level 1: top 12 bits ----
    for (int i = tid; i < 4096; i += 1024) hist[i] = 0;
    if (tid == 0) { sh_need = KK; sh_take = 0; }
    __syncthreads();
    for (int n = tid; n < NN; n += 1024) {
        float s = sc[n];
        if (s > SCORE_T) hist_add(hist, (int)(__float_as_uint(s) >> 20));
    }
    __syncthreads();
    scan_boundary(hist, gsum, 128, tid, &sh_sel, &sh_need, &sh_take);
    int take = sh_take;
    int B1 = sh_sel;
    unsigned Kt = 1u;

    if (!take) {
        // ---- level 2: bits 19..8 ----
        for (int i = tid; i < 4096; i += 1024) hist[i] = 0;
        __syncthreads();
        for (int n = tid; n < NN; n += 1024) {
            float s = sc[n];
            if (s > SCORE_T) {
                unsigned k = __float_as_uint(s);
                if ((int)(k >> 20) == B1) hist_add(hist, (int)((k >> 8) & 0xFFF));
            }
        }
        __syncthreads();
        scan_boundary(hist, gsum, 128, tid, &sh_sel, &sh_need, &sh_take);
        int B2 = sh_sel;
        unsigned P2 = ((unsigned)B1 << 12) | (unsigned)B2;

        // ---- level 3: bits 7..0 ----
        for (int i = tid; i < 256; i += 1024) hist[i] = 0;
        __syncthreads();
        for (int n = tid; n < NN; n += 1024) {
            float s = sc[n];
            if (s > SCORE_T) {
                unsigned k = __float_as_uint(s);
                if ((k >> 8) == P2) hist_add(hist, (int)(k & 0xFF));
            }
        }
        __syncthreads();
        scan_boundary(hist, gsum, 8, tid, &sh_sel, &sh_need, &sh_take);
        int B3 = sh_sel;
        Kt = ((unsigned)B1 << 20) | ((unsigned)B2 << 8) | (unsigned)B3;
    }

    // ---- gather candidates with key >= Kt ----
    for (int i = tid; i < 2048; i += 1024) arr[i] = 0ull;
    if (tid == 0) sh_cnt = 0;
    __syncthreads();
    for (int n = tid; n < NN; n += 1024) {
        float s = sc[n];
        if (s > SCORE_T) {
            unsigned k = __float_as_uint(s);
            if (k >= Kt) {
                int p = atomicAdd(&sh_cnt, 1);
                if (p < 2048)
                    arr[p] = ((unsigned long long)k << 32) | (unsigned long long)(0xFFFFFFFFu - (unsigned)n);
            }
        }
    }
    __syncthreads();

    // ---- bitonic sort 2048, descending (score desc, idx asc on ties) ----
    for (int k = 2; k <= 2048; k <<= 1)
        for (int j = k >> 1; j > 0; j >>= 1) {
            __syncthreads();
            for (int i = tid; i < 2048; i += 1024) {
                int ixj = i ^ j;
                if (ixj > i) {
                    unsigned long long a = arr[i], b = arr[ixj];
                    if (((i & k) == 0) ? (a < b) : (a > b)) { arr[i] = b; arr[ixj] = a; }
                }
            }
        }
    __syncthreads();

    if (tid < KK) {
        unsigned long long v = arr[tid];
        float val;
        int idx;
        if (v) {
            val = __uint_as_float((unsigned)(v >> 32));
            idx = (int)(0xFFFFFFFFu - (unsigned)v);
        } else {
            val = -1.0f;     // fewer than 1000 candidates (padding; cannot surface in output)
            idx = tid;
        }
        g_topval[bc * KK + tid] = val;
        g_topidx[bc * KK + tid] = idx;
    }
}

// ---------------- K3: decode selected boxes ----------------
__global__ __launch_bounds__(256) void decode_kernel(const float4* __restrict__ anchors,
                                                     const float4* __restrict__ deltas) {
    int g = blockIdx.x * 256 + threadIdx.x;
    if (g >= BC * KK) return;
    int bc = g / KK;
    int b = bc / CC;
    int a = g_topidx[g];
    float4 an = anchors[a];
    float4 dl = deltas[(size_t)b * NN + a];
    float acx = (an.x + an.z) * 0.5f, acy = (an.y + an.w) * 0.5f;
    float aw = fmaxf(an.z - an.x, 1.0f), ah = fmaxf(an.w - an.y, 1.0f);
    float cx = dl.x * aw + acx, cy = dl.y * ah + acy;
    float w = expf(fminf(dl.z, 4.0f)) * aw;
    float h = expf(fminf(dl.w, 4.0f)) * ah;
    g_topbox[g] = make_float4(cx - w * 0.5f, cy - h * 0.5f, cx + w * 0.5f, cy + h * 0.5f);
}

// ---------------- K4: NMS suppression bitmatrix ----------------
__global__ __launch_bounds__(512) void nms_mask_kernel() {
    int bc = blockIdx.x;
    int tid = threadIdx.x;
    __shared__ float4 sb[KK];
    __shared__ float sa[KK];
    for (int i = tid; i < KK; i += 512) {
        float4 bx = g_topbox[bc * KK + i];
        sb[i] = bx;
        sa[i] = (bx.z - bx.x) * (bx.w - bx.y);
    }
    __syncthreads();
    if (tid < 500) {
#pragma unroll 1
        for (int rr = 0; rr < 2; rr++) {
            int i = rr ? (999 - tid) : tid;   // pair rows for load balance
            float4 bi = sb[i];
            float ai = sa[i];
            unsigned long long* row = &g_mask[((size_t)bc * KK + i) * 16];
            for (int w = 0; w < 16; w++) {
                unsigned long long bits = 0ull;
                int jlo = w * 64;
                if (jlo + 63 > i) {
                    int j0 = max(jlo, i + 1);
                    int j1 = min(KK, jlo + 64);
                    for (int j = j0; j < j1; j++) {
                        float4 bj = sb[j];
                        float x1 = fmaxf(bi.x, bj.x), y1 = fmaxf(bi.y, bj.y);
                        float x2 = fminf(bi.z, bj.z), y2 = fminf(bi.w, bj.w);
                        float inter = fmaxf(x2 - x1, 0.0f) * fmaxf(y2 - y1, 0.0f);
                        float un = fmaxf(ai + sa[j] - inter, 1e-6f);
                        float iou = __fdiv_rn(inter, un);
                        if (iou > IOU_T) bits |= 1ull << (j - jlo);
                    }
                }
                row[w] = bits;
            }
        }
    }
}

// ---------------- K5: sequential greedy reduction over bitmatrix ----------------
__global__ __launch_bounds__(32) void nms_reduce_kernel() {
    int bc = blockIdx.x;
    int lane = threadIdx.x;
    unsigned long long removed = 0ull;
    int cnt = 0;
    for (int i = 0; i < KK; i++) {
        int w = i >> 6;
        unsigned long long r = __shfl_sync(0xFFFFFFFFu, removed, w);
        bool keep = !((r >> (i & 63)) & 1ull);
        unsigned long long m = 0ull;
        if (lane < 16) m = g_mask[((size_t)bc * KK + i) * 16 + lane];
        if (keep) removed |= m;
        if (lane == 0) {
            float v = g_topval[bc * KK + i];
            float out = (keep && v > SCORE_T) ? v : 0.0f;
            g_val[bc * KK + i] = out;
            if (out > 0.0f) {
                g_cval[bc * KK + cnt] = out;   // survivors stay score-descending
                g_cidx[bc * KK + cnt] = i;
                cnt++;
            }
        }
    }
    if (lane == 0) g_cnt[bc] = cnt;
}

// ---------------- K6: per-image top-100 over 9 classes ----------------
__global__ __launch_bounds__(512) void final_kernel(float* __restrict__ out) {
    int b = blockIdx.x;
    int tid = threadIdx.x;
    __shared__ unsigned long long arr[1024];
    for (int i = tid; i < 1024; i += 512) arr[i] = 0ull;
    __syncthreads();
    // only the top-100 of each class can reach the global top-100
    for (int s = tid; s < 900; s += 512) {
        int c = s / 100, r = s % 100;
        int bc = b * 9 + c;
        if (r < g_cnt[bc]) {
            float v = g_cval[bc * KK + r];
            int k = g_cidx[bc * KK + r];
            unsigned flat = (unsigned)(c * KK + k);
            arr[s] = ((unsigned long long)__float_as_uint(v) << 32) |
                     (unsigned long long)(0xFFFFFFFFu - flat);
        }
    }
    __syncthreads();
    for (int k = 2; k <= 1024; k <<= 1)
        for (int j = k >> 1; j > 0; j >>= 1) {
            __syncthreads();
            for (int i = tid; i < 1024; i += 512) {
                int ixj = i ^ j;
                if (ixj > i) {
                    unsigned long long a = arr[i], bv = arr[ixj];
                    if (((i & k) == 0) ? (a < bv) : (a > bv)) { arr[i] = bv; arr[ixj] = a; }
                }
            }
        }
    __syncthreads();

    float* o = out + (size_t)b * MAXDET * 6;
    if (tid < MAXDET) {
        unsigned long long v = arr[tid];
        if (v) {
            unsigned flat = 0xFFFFFFFFu - (unsigned)v;
            int c = flat / KK, k2 = flat % KK;
            float4 bx = g_topbox[(b * 9 + c) * KK + k2];
            float scv = __uint_as_float((unsigned)(v >> 32));
            o[tid * 6 + 0] = bx.x; o[tid * 6 + 1] = bx.y;
            o[tid * 6 + 2] = bx.z; o[tid * 6 + 3] = bx.w;
            o[tid * 6 + 4] = scv;  o[tid * 6 + 5] = (float)c;
        }
    }
    __syncthreads();
    // exact-tie fallback: < 100 positive detections -> zero-score entries by ascending flat idx
    if (tid == 0 && arr[MAXDET - 1] == 0ull) {
        int f = 0;
        for (int t = 0; t < MAXDET; t++) {
            if (arr[t]) continue;
            while (f < 9000 && g_val[(size_t)b * 9000 + f] != 0.0f) f++;
            int c = 0, k2 = 0;
            float4 bx = make_float4(0.f, 0.f, 0.f, 0.f);
            if (f < 9000) {
                c = f / KK; k2 = f % KK;
                bx = g_topbox[(b * 9 + c) * KK + k2];
                f++;
            }
            o[t * 6 + 0] = bx.x; o[t * 6 + 1] = bx.y;
            o[t * 6 + 2] = bx.z; o[t * 6 + 3] = bx.w;
            o[t * 6 + 4] = 0.0f; o[t * 6 + 5] = (float)c;
        }
    }
}

// ---------------- launch ----------------
extern "C" void kernel_launch(void* const* d_in, const int* in_sizes, int n_in,
                              void* d_out, int out_size) {
    (void)in_sizes; (void)n_in; (void)out_size;
    const float* anchors = (const float*)d_in[0];
    const float* deltas  = (const float*)d_in[1];
    const float* cls     = (const float*)d_in[2];
    const float* obj     = (const float*)d_in[3];
    float* out = (float*)d_out;

    score_kernel<<<dim3(NN / 256, BB), 256>>>(cls, obj);
    select_kernel<<<BC, 1024>>>();
    decode_kernel<<<(BC * KK + 255) / 256, 256>>>((const float4*)anchors, (const float4*)deltas);
    nms_mask_kernel<<<BC, 512>>>();
    nms_reduce_kernel<<<BC, 32>>>();
    final_kernel<<<BB, 512>>>(out);
}

// round 2
// speedup vs baseline: 1.0772x; 1.0772x over previous
#include <cuda_runtime.h>
#include <cuda_bf16.h>
#include <cstdint>

#define NN 193536
#define BB 16
#define CC 9
#define KK 1000
#define BC 144            // BB*CC
#define MAXDET 100
#define SCORE_T 0.05f
#define IOU_T 0.5f

// ---------------- scratch (static device globals; no dynamic alloc) ----------------
__device__ float              g_scores[(size_t)BC * NN];       // ~111.5 MB, layout [(b*9+c)][n]
__device__ float              g_topval[BC * KK];
__device__ int                g_topidx[BC * KK];
__device__ float4             g_topbox[BC * KK];
__device__ unsigned long long g_mask[(size_t)BC * KK * 16];    // 18.4 MB suppression bitmatrix
__device__ float              g_val[BC * KK];                  // post-NMS score (0 for invalid)
__device__ float              g_cval[BC * KK];                 // compacted survivors (desc order)
__device__ int                g_cidx[BC * KK];
__device__ int                g_cnt[BC];

// ---------------- K1: sigmoid + transpose scores to class-major ----------------
__global__ __launch_bounds__(256) void score_kernel(const float* __restrict__ cls,
                                                    const float* __restrict__ obj) {
    int b = blockIdx.y;
    int n0 = blockIdx.x * 256;
    int tid = threadIdx.x;
    __shared__ float sh[256 * 9];
    const float* src = cls + ((size_t)b * NN + n0) * 9;
    for (int i = tid; i < 2304; i += 256) sh[i] = src[i];
    __syncthreads();
    int n = n0 + tid;
    float so = 1.0f / (1.0f + expf(-obj[(size_t)b * NN + n]));
#pragma unroll
    for (int c = 0; c < 9; c++) {
        float s = 1.0f / (1.0f + expf(-sh[tid * 9 + c]));
        g_scores[((size_t)(b * 9 + c)) * NN + n] = s * so;
    }
}

// ---------------- scan helper: find boundary bin from top, given `need` ----------------
__device__ __forceinline__ void scan_boundary(unsigned* hist, unsigned* gsum, int NG,
                                              int tid, int* sh_sel, int* sh_need, int* sh_take) {
    if (tid < NG) {
        unsigned t = 0;
        int base = tid * 32;
#pragma unroll 8
        for (int i = 0; i < 32; i++) t += hist[base + i];
        gsum[tid] = t;
    }
    __syncthreads();
    if (tid == 0) {
        int need = *sh_need;
        unsigned acc = 0;
        int g = NG - 1;
        for (; g >= 0; g--) {
            if (acc + gsum[g] >= (unsigned)need) break;
            acc += gsum[g];
        }
        if (g < 0) {
            *sh_take = 1;  // fewer than `need` candidates total
        } else {
            int bin = g * 32 + 31;
            for (;; bin--) {
                if (acc + hist[bin] >= (unsigned)need) break;
                acc += hist[bin];
            }
            *sh_sel = bin;
            *sh_need = need - (int)acc;
        }
    }
    __syncthreads();
}

__device__ __forceinline__ void hist_add(unsigned* hist, int bin) {
    // warp-aggregated atomic
    unsigned m = __match_any_sync(__activemask(), bin);
    int leader = __ffs(m) - 1;
    if ((threadIdx.x & 31) == leader) atomicAdd(&hist[bin], __popc(m));
}

// ---------------- K2: per-(b,c) exact top-1000 (radix-select 8/12/12 + bitonic) ----------------
__global__ __launch_bounds__(1024) void select_kernel() {
    int bc = blockIdx.x;
    int tid = threadIdx.x;
    int lane = tid & 31;
    int wid = tid >> 5;
    const float* sc = g_scores + (size_t)bc * NN;

    // 32KB overlay:
    //  phase A (pass1): wh[32][256] per-warp hists
    //  phase B (pass2/3): hist[4096] at +16KB
    //  phase C (gather/sort): arr[2048] at +0
    __shared__ __align__(16) unsigned char sraw[32768];
    unsigned* wh = (unsigned*)sraw;
    unsigned* hist = (unsigned*)(sraw + 16384);
    unsigned long long* arr = (unsigned long long*)sraw;
    __shared__ unsigned merged[256];
    __shared__ unsigned gsum[128];
    __shared__ int sh_sel, sh_need, sh_take, sh_cnt;

    // ---- pass 1: top 8 bits, per-warp private hists (no cross-warp contention) ----
    for (int i = tid; i < 8192; i += 1024) wh[i] = 0;
    if (tid == 0) { sh_need = KK; sh_take = 0; }
    __syncthreads();
    for (int n = tid; n < NN; n += 1024) {
        float s = sc[n];
        if (s > SCORE_T) {
            int bin = (int)(__float_as_uint(s) >> 24);
            unsigned m = __match_any_sync(__activemask(), bin);
            if (lane == __ffs(m) - 1) atomicAdd(&wh[wid * 256 + bin], __popc(m));
        }
    }
    __syncthreads();
    if (tid < 256) {
        unsigned t = 0;
#pragma unroll
        for (int w = 0; w < 32; w++) t += wh[w * 256 + tid];
        merged[tid] = t;
    }
    __syncthreads();
    scan_boundary(merged, gsum, 8, tid, &sh_sel, &sh_need, &sh_take);
    int take = sh_take;
    int B1 = sh_sel;
    unsigned Kt = 1u;

    if (!take) {
        // ---- pass 2: bits 23..12 within B1 ----
        for (int i = tid; i < 4096; i += 1024) hist[i] = 0;
        __syncthreads();
        for (int n = tid; n < NN; n += 1024) {
            float s = sc[n];
            if (s > SCORE_T) {
                unsigned k = __float_as_uint(s);
                if ((int)(k >> 24) == B1) hist_add(hist, (int)((k >> 12) & 0xFFF));
            }
        }
        __syncthreads();
        scan_boundary(hist, gsum, 128, tid, &sh_sel, &sh_need, &sh_take);
        int B2 = sh_sel;
        unsigned P2 = ((unsigned)B1 << 12) | (unsigned)B2;   // top 20 bits

        // ---- pass 3: bits 11..0 within P2 (full 32-bit threshold) ----
        for (int i = tid; i < 4096; i += 1024) hist[i] = 0;
        __syncthreads();
        for (int n = tid; n < NN; n += 1024) {
            float s = sc[n];
            if (s > SCORE_T) {
                unsigned k = __float_as_uint(s);
                if ((k >> 12) == P2) hist_add(hist, (int)(k & 0xFFF));
            }
        }
        __syncthreads();
        scan_boundary(hist, gsum, 128, tid, &sh_sel, &sh_need, &sh_take);
        int B3 = sh_sel;
        Kt = (P2 << 12) | (unsigned)B3;
    }

    // ---- gather candidates with key >= Kt ----
    __syncthreads();
    for (int i = tid; i < 2048; i += 1024) arr[i] = 0ull;
    if (tid == 0) sh_cnt = 0;
    __syncthreads();
    for (int n = tid; n < NN; n += 1024) {
        float s = sc[n];
        if (s > SCORE_T) {
            unsigned k = __float_as_uint(s);
            if (k >= Kt) {
                int p = atomicAdd(&sh_cnt, 1);
                if (p < 2048)
                    arr[p] = ((unsigned long long)k << 32) | (unsigned long long)(0xFFFFFFFFu - (unsigned)n);
            }
        }
    }
    __syncthreads();

    // ---- bitonic sort 2048, descending (score desc, idx asc on ties) ----
    for (int k = 2; k <= 2048; k <<= 1)
        for (int j = k >> 1; j > 0; j >>= 1) {
            __syncthreads();
            for (int i = tid; i < 2048; i += 1024) {
                int ixj = i ^ j;
                if (ixj > i) {
                    unsigned long long a = arr[i], b = arr[ixj];
                    if (((i & k) == 0) ? (a < b) : (a > b)) { arr[i] = b; arr[ixj] = a; }
                }
            }
        }
    __syncthreads();

    if (tid < KK) {
        unsigned long long v = arr[tid];
        float val;
        int idx;
        if (v) {
            val = __uint_as_float((unsigned)(v >> 32));
            idx = (int)(0xFFFFFFFFu - (unsigned)v);
        } else {
            val = -1.0f;     // padding; cannot surface in output
            idx = tid;
        }
        g_topval[bc * KK + tid] = val;
        g_topidx[bc * KK + tid] = idx;
    }
}

// ---------------- K3: decode selected boxes ----------------
__global__ __launch_bounds__(256) void decode_kernel(const float4* __restrict__ anchors,
                                                     const float4* __restrict__ deltas) {
    int g = blockIdx.x * 256 + threadIdx.x;
    if (g >= BC * KK) return;
    int bc = g / KK;
    int b = bc / CC;
    int a = g_topidx[g];
    float4 an = anchors[a];
    float4 dl = deltas[(size_t)b * NN + a];
    float acx = (an.x + an.z) * 0.5f, acy = (an.y + an.w) * 0.5f;
    float aw = fmaxf(an.z - an.x, 1.0f), ah = fmaxf(an.w - an.y, 1.0f);
    float cx = dl.x * aw + acx, cy = dl.y * ah + acy;
    float w = expf(fminf(dl.z, 4.0f)) * aw;
    float h = expf(fminf(dl.w, 4.0f)) * ah;
    g_topbox[g] = make_float4(cx - w * 0.5f, cy - h * 0.5f, cx + w * 0.5f, cy + h * 0.5f);
}

// ---------------- K4: NMS suppression bitmatrix (warp-per-unit, ballot) ----------------
__global__ __launch_bounds__(1024) void nms_mask_kernel() {
    int bc = blockIdx.x;
    int tid = threadIdx.x;
    int lane = tid & 31;
    int wid = tid >> 5;
    __shared__ float4 sb[KK];
    __shared__ float sa[KK];
    for (int i = tid; i < KK; i += 1024) {
        float4 bx = g_topbox[bc * KK + i];
        sb[i] = bx;
        sa[i] = (bx.z - bx.x) * (bx.w - bx.y);
    }
    __syncthreads();
    int gw = blockIdx.y * 32 + wid;   // 0..127 global warp within bc
    for (int i = gw; i < KK; i += 128) {
        float4 bi = sb[i];
        float ai = sa[i];
        unsigned long long* row = &g_mask[((size_t)bc * KK + i) * 16];
        int w0 = i >> 6;
        for (int w = w0; w < 16; w++) {
            int j1 = (w << 6) + lane;
            int j2 = j1 + 32;
            bool s1 = false, s2 = false;
            if (j1 > i && j1 < KK) {
                float4 bj = sb[j1];
                float x1 = fmaxf(bi.x, bj.x), y1 = fmaxf(bi.y, bj.y);
                float x2 = fminf(bi.z, bj.z), y2 = fminf(bi.w, bj.w);
                float inter = fmaxf(x2 - x1, 0.0f) * fmaxf(y2 - y1, 0.0f);
                float un = fmaxf(ai + sa[j1] - inter, 1e-6f);
                s1 = inter > 0.5f * un;
            }
            if (j2 > i && j2 < KK) {
                float4 bj = sb[j2];
                float x1 = fmaxf(bi.x, bj.x), y1 = fmaxf(bi.y, bj.y);
                float x2 = fminf(bi.z, bj.z), y2 = fminf(bi.w, bj.w);
                float inter = fmaxf(x2 - x1, 0.0f) * fmaxf(y2 - y1, 0.0f);
                float un = fmaxf(ai + sa[j2] - inter, 1e-6f);
                s2 = inter > 0.5f * un;
            }
            unsigned b1 = __ballot_sync(0xFFFFFFFFu, s1);
            unsigned b2 = __ballot_sync(0xFFFFFFFFu, s2);
            if (lane == 0) row[w] = ((unsigned long long)b2 << 32) | (unsigned long long)b1;
        }
    }
}

// ---------------- K5: sequential greedy reduction (prefetched) ----------------
__global__ __launch_bounds__(32) void nms_reduce_kernel() {
    int bc = blockIdx.x;
    int lane = threadIdx.x;
    const unsigned long long* mrow = g_mask + (size_t)bc * KK * 16;
    unsigned long long removed = 0ull;
    unsigned long long m = (lane < 16) ? mrow[lane] : 0ull;   // prefetch row 0
    int cnt = 0;
    for (int i = 0; i < KK; i++) {
        unsigned long long mn = 0ull;
        if (i + 1 < KK && lane < 16) mn = mrow[(size_t)(i + 1) * 16 + lane];  // prefetch next row
        int w0 = i >> 6;
        unsigned long long mm = (lane < w0) ? 0ull : m;       // sanitize sub-diagonal words
        unsigned long long r = __shfl_sync(0xFFFFFFFFu, removed, w0);
        bool keep = !((r >> (i & 63)) & 1ull);
        if (keep) removed |= mm;
        if (lane == 0) {
            float v = g_topval[bc * KK + i];
            float outv = (keep && v > SCORE_T) ? v : 0.0f;
            g_val[bc * KK + i] = outv;
            if (outv > 0.0f) {
                g_cval[bc * KK + cnt] = outv;   // survivors stay score-descending
                g_cidx[bc * KK + cnt] = i;
                cnt++;
            }
        }
        m = mn;
    }
    if (lane == 0) g_cnt[bc] = cnt;
}

// ---------------- K6: per-image top-100 over 9 classes ----------------
__global__ __launch_bounds__(512) void final_kernel(float* __restrict__ out) {
    int b = blockIdx.x;
    int tid = threadIdx.x;
    __shared__ unsigned long long arr[1024];
    for (int i = tid; i < 1024; i += 512) arr[i] = 0ull;
    __syncthreads();
    // only the top-100 of each class can reach the global top-100
    for (int s = tid; s < 900; s += 512) {
        int c = s / 100, r = s % 100;
        int bc = b * 9 + c;
        if (r < g_cnt[bc]) {
            float v = g_cval[bc * KK + r];
            int k = g_cidx[bc * KK + r];
            unsigned flat = (unsigned)(c * KK + k);
            arr[s] = ((unsigned long long)__float_as_uint(v) << 32) |
                     (unsigned long long)(0xFFFFFFFFu - flat);
        }
    }
    __syncthreads();
    for (int k = 2; k <= 1024; k <<= 1)
        for (int j = k >> 1; j > 0; j >>= 1) {
            __syncthreads();
            for (int i = tid; i < 1024; i += 512) {
                int ixj = i ^ j;
                if (ixj > i) {
                    unsigned long long a = arr[i], bv = arr[ixj];
                    if (((i & k) == 0) ? (a < bv) : (a > bv)) { arr[i] = bv; arr[ixj] = a; }
                }
            }
        }
    __syncthreads();

    float* o = out + (size_t)b * MAXDET * 6;
    if (tid < MAXDET) {
        unsigned long long v = arr[tid];
        if (v) {
            unsigned flat = 0xFFFFFFFFu - (unsigned)v;
            int c = flat / KK, k2 = flat % KK;
            float4 bx = g_topbox[(b * 9 + c) * KK + k2];
            float scv = __uint_as_float((unsigned)(v >> 32));
            o[tid * 6 + 0] = bx.x; o[tid * 6 + 1] = bx.y;
            o[tid * 6 + 2] = bx.z; o[tid * 6 + 3] = bx.w;
            o[tid * 6 + 4] = scv;  o[tid * 6 + 5] = (float)c;
        }
    }
    __syncthreads();
    // exact-tie fallback: < 100 positive detections -> zero-score entries by ascending flat idx
    if (tid == 0 && arr[MAXDET - 1] == 0ull) {
        int f = 0;
        for (int t = 0; t < MAXDET; t++) {
            if (arr[t]) continue;
            while (f < 9000 && g_val[(size_t)b * 9000 + f] != 0.0f) f++;
            int c = 0, k2 = 0;
            float4 bx = make_float4(0.f, 0.f, 0.f, 0.f);
            if (f < 9000) {
                c = f / KK; k2 = f % KK;
                bx = g_topbox[(b * 9 + c) * KK + k2];
                f++;
            }
            o[t * 6 + 0] = bx.x; o[t * 6 + 1] = bx.y;
            o[t * 6 + 2] = bx.z; o[t * 6 + 3] = bx.w;
            o[t * 6 + 4] = 0.0f; o[t * 6 + 5] = (float)c;
        }
    }
}

// ---------------- launch ----------------
extern "C" void kernel_launch(void* const* d_in, const int* in_sizes, int n_in,
                              void* d_out, int out_size) {
    (void)in_sizes; (void)n_in; (void)out_size;
    const float* anchors = (const float*)d_in[0];
    const float* deltas  = (const float*)d_in[1];
    const float* cls     = (const float*)d_in[2];
    const float* obj     = (const float*)d_in[3];
    float* out = (float*)d_out;

    score_kernel<<<dim3(NN / 256, BB), 256>>>(cls, obj);
    select_kernel<<<BC, 1024>>>();
    decode_kernel<<<(BC * KK + 255) / 256, 256>>>((const float4*)anchors, (const float4*)deltas);
    nms_mask_kernel<<<dim3(BC, 4), 1024>>>();
    nms_reduce_kernel<<<BC, 32>>>();
    final_kernel<<<BB, 512>>>(out);
}

// round 3
// speedup vs baseline: 1.6566x; 1.5379x over previous
#include <cuda_runtime.h>
#include <cuda_bf16.h>
#include <cstdint>

#define NN 193536
#define BB 16
#define CC 9
#define KK 1000
#define BC 144            // BB*CC
#define MAXDET 100
#define SCORE_T 0.05f
#define IOU_T 0.5f

// keys are positive floats in (0.05, 1): 20-bit prefixes span [0x3D4CC, 0x3F7FF]
#define P_LO 0x3D4CCu
#define HB 9012
#define HBPAD 9024        // padded to 282*32
#define KT_MIN 0x3D4CCCCEu   // smallest uint key with float > 0.05f

// ---------------- scratch (static device globals; no dynamic alloc) ----------------
__device__ float              g_scores[(size_t)BC * NN];       // ~111.5 MB, [(b*9+c)][n]
__device__ float              g_topval[BC * KK];
__device__ float4             g_topbox[BC * KK];
__device__ unsigned long long g_mask[(size_t)BC * KK * 16];    // 18.4 MB suppression bitmatrix
__device__ float              g_val[BC * KK];                  // post-NMS score (0 for invalid)
__device__ float              g_cval[BC * KK];                 // compacted survivors (desc order)
__device__ int                g_cidx[BC * KK];
__device__ int                g_cnt[BC];

// ---------------- K1: sigmoid + transpose scores to class-major ----------------
__global__ __launch_bounds__(256) void score_kernel(const float* __restrict__ cls,
                                                    const float* __restrict__ obj) {
    int b = blockIdx.y;
    int n0 = blockIdx.x * 256;
    int tid = threadIdx.x;
    __shared__ float sh[256 * 9];
    const float* src = cls + ((size_t)b * NN + n0) * 9;
    for (int i = tid; i < 2304; i += 256) sh[i] = src[i];
    __syncthreads();
    int n = n0 + tid;
    float so = 1.0f / (1.0f + expf(-obj[(size_t)b * NN + n]));
#pragma unroll
    for (int c = 0; c < 9; c++) {
        float s = 1.0f / (1.0f + expf(-sh[tid * 9 + c]));
        g_scores[((size_t)(b * 9 + c)) * NN + n] = s * so;
    }
}

// ---------------- scan helper: boundary bin from top, given remaining need ----------------
__device__ __forceinline__ void scan_boundary(unsigned* hist, unsigned* gsum, int NG,
                                              int tid, int* sh_sel, int* sh_need,
                                              int* sh_take, unsigned* sh_gat) {
    if (tid < NG) {
        unsigned t = 0;
        int base = tid * 32;
#pragma unroll 8
        for (int i = 0; i < 32; i++) t += hist[base + i];
        gsum[tid] = t;
    }
    __syncthreads();
    if (tid == 0) {
        int need = *sh_need;
        unsigned acc = 0;
        int g = NG - 1;
        for (; g >= 0; g--) {
            if (acc + gsum[g] >= (unsigned)need) break;
            acc += gsum[g];
        }
        if (g < 0) {
            *sh_take = 1;  // fewer than `need` candidates total
        } else {
            int bin = g * 32 + 31;
            for (;; bin--) {
                if (acc + hist[bin] >= (unsigned)need) break;
                acc += hist[bin];
            }
            *sh_sel = bin;
            *sh_need = need - (int)acc;          // remaining need inside boundary bin
            *sh_gat = acc + hist[bin];           // total items with key >= bin prefix
        }
    }
    __syncthreads();
}

__device__ __forceinline__ void hist_add(unsigned* hist, int bin) {
    unsigned m = __match_any_sync(__activemask(), bin);
    int leader = __ffs(m) - 1;
    if ((threadIdx.x & 31) == leader) atomicAdd(&hist[bin], __popc(m));
}

// ---------------- K2: per-(b,c) exact top-1000 (1 hist pass + gather) + decode ----------------
__global__ __launch_bounds__(1024) void select_kernel(const float4* __restrict__ anchors,
                                                      const float4* __restrict__ deltas) {
    int bc = blockIdx.x;
    int tid = threadIdx.x;
    const float4* sc4 = (const float4*)(g_scores + (size_t)bc * NN);

    __shared__ __align__(16) unsigned char sraw[HBPAD * 4];   // 36 KB overlay
    unsigned* hist = (unsigned*)sraw;
    unsigned long long* arr = (unsigned long long*)sraw;      // 16 KB, overlays hist
    __shared__ unsigned gsum[288];
    __shared__ int sh_sel, sh_need, sh_take, sh_cnt;
    __shared__ unsigned sh_gat;

    // ---- pass A: histogram over 20-bit prefixes (monotone, low contention) ----
    for (int i = tid; i < HBPAD; i += 1024) hist[i] = 0;
    if (tid == 0) { sh_need = KK; sh_take = 0; }
    __syncthreads();
    for (int n4 = tid; n4 < NN / 4; n4 += 1024) {
        float4 v = sc4[n4];
        float sv[4] = {v.x, v.y, v.z, v.w};
#pragma unroll
        for (int c = 0; c < 4; c++) {
            float s = sv[c];
            if (s > SCORE_T) {
                int bin = (int)(__float_as_uint(s) >> 12) - (int)P_LO;
                bin = min(max(bin, 0), HB - 1);
                hist_add(hist, bin);
            }
        }
    }
    __syncthreads();
    scan_boundary(hist, gsum, 282, tid, &sh_sel, &sh_need, &sh_take, &sh_gat);

    unsigned Kt;
    if (sh_take) {
        Kt = KT_MIN;                       // fewer than 1000 total: take everything > thresh
    } else {
        unsigned prefix = P_LO + (unsigned)sh_sel;
        Kt = prefix << 12;
        if (sh_gat > 2048u) {
            // ---- rare refinement: low 12 bits within boundary prefix ----
            __syncthreads();
            for (int i = tid; i < 4096; i += 1024) hist[i] = 0;
            __syncthreads();
            for (int n4 = tid; n4 < NN / 4; n4 += 1024) {
                float4 v = sc4[n4];
                float sv[4] = {v.x, v.y, v.z, v.w};
#pragma unroll
                for (int c = 0; c < 4; c++) {
                    float s = sv[c];
                    if (s > SCORE_T) {
                        unsigned k = __float_as_uint(s);
                        if ((k >> 12) == prefix) hist_add(hist, (int)(k & 0xFFF));
                    }
                }
            }
            __syncthreads();
            scan_boundary(hist, gsum, 128, tid, &sh_sel, &sh_need, &sh_take, &sh_gat);
            Kt = (prefix << 12) | (unsigned)sh_sel;    // exact 32-bit threshold
        }
    }

    // ---- gather candidates with key >= Kt ----
    __syncthreads();
    for (int i = tid; i < 2048; i += 1024) arr[i] = 0ull;
    if (tid == 0) sh_cnt = 0;
    __syncthreads();
    for (int n4 = tid; n4 < NN / 4; n4 += 1024) {
        float4 v = sc4[n4];
        float sv[4] = {v.x, v.y, v.z, v.w};
#pragma unroll
        for (int c = 0; c < 4; c++) {
            float s = sv[c];
            if (s > SCORE_T) {
                unsigned k = __float_as_uint(s);
                if (k >= Kt) {
                    int p = atomicAdd(&sh_cnt, 1);
                    unsigned n = (unsigned)(n4 * 4 + c);
                    if (p < 2048)
                        arr[p] = ((unsigned long long)k << 32) |
                                 (unsigned long long)(0xFFFFFFFFu - n);
                }
            }
        }
    }
    __syncthreads();

    // ---- bitonic sort 2048 desc (score desc, idx asc on ties) ----
    for (int k = 2; k <= 2048; k <<= 1)
        for (int j = k >> 1; j > 0; j >>= 1) {
            __syncthreads();
            for (int i = tid; i < 2048; i += 1024) {
                int ixj = i ^ j;
                if (ixj > i) {
                    unsigned long long a = arr[i], b = arr[ixj];
                    if (((i & k) == 0) ? (a < b) : (a > b)) { arr[i] = b; arr[ixj] = a; }
                }
            }
        }
    __syncthreads();

    // ---- epilogue: write topval + decode box inline ----
    if (tid < KK) {
        unsigned long long v = arr[tid];
        float val;
        int idx;
        if (v) {
            val = __uint_as_float((unsigned)(v >> 32));
            idx = (int)(0xFFFFFFFFu - (unsigned)v);
        } else {
            val = -1.0f;    // padding; cannot surface in output
            idx = tid;
        }
        g_topval[bc * KK + tid] = val;
        int b = bc / CC;
        float4 an = anchors[idx];
        float4 dl = deltas[(size_t)b * NN + idx];
        float acx = (an.x + an.z) * 0.5f, acy = (an.y + an.w) * 0.5f;
        float aw = fmaxf(an.z - an.x, 1.0f), ah = fmaxf(an.w - an.y, 1.0f);
        float cx = dl.x * aw + acx, cy = dl.y * ah + acy;
        float w = expf(fminf(dl.z, 4.0f)) * aw;
        float h = expf(fminf(dl.w, 4.0f)) * ah;
        g_topbox[bc * KK + tid] = make_float4(cx - w * 0.5f, cy - h * 0.5f,
                                              cx + w * 0.5f, cy + h * 0.5f);
    }
}

// ---------------- K3: NMS suppression bitmatrix (row-pair per warp, ballot) ----------------
__global__ __launch_bounds__(1024) void nms_mask_kernel() {
    int bc = blockIdx.x;
    int tid = threadIdx.x;
    int lane = tid & 31;
    int wid = tid >> 5;
    __shared__ float4 sb[KK];
    __shared__ float sa[KK];
    for (int i = tid; i < KK; i += 1024) {
        float4 bx = g_topbox[bc * KK + i];
        sb[i] = bx;
        sa[i] = (bx.z - bx.x) * (bx.w - bx.y);
    }
    __syncthreads();
    int gw = blockIdx.y * 32 + wid;   // 0..127 global warp within bc
    for (int p = gw; p < KK / 2; p += 128) {
        int i0 = p * 2, i1 = i0 + 1;
        float4 bA = sb[i0], bB = sb[i1];
        float aA = sa[i0], aB = sa[i1];
        unsigned long long* r0 = &g_mask[((size_t)bc * KK + i0) * 16];
        unsigned long long* r1 = r0 + 16;
        for (int w = i0 >> 6; w < 16; w++) {
            int j1 = (w << 6) + lane;
            int j2 = j1 + 32;
            bool sA1 = false, sA2 = false, sB1 = false, sB2 = false;
            {
                float4 bj = sb[j1];
                float aj = sa[j1];
                float x1a = fmaxf(bA.x, bj.x), y1a = fmaxf(bA.y, bj.y);
                float x2a = fminf(bA.z, bj.z), y2a = fminf(bA.w, bj.w);
                float ia = fmaxf(x2a - x1a, 0.0f) * fmaxf(y2a - y1a, 0.0f);
                sA1 = (j1 > i0) && (j1 < KK) && (ia > 0.5f * fmaxf(aA + aj - ia, 1e-6f));
                float x1b = fmaxf(bB.x, bj.x), y1b = fmaxf(bB.y, bj.y);
                float x2b = fminf(bB.z, bj.z), y2b = fminf(bB.w, bj.w);
                float ib = fmaxf(x2b - x1b, 0.0f) * fmaxf(y2b - y1b, 0.0f);
                sB1 = (j1 > i1) && (j1 < KK) && (ib > 0.5f * fmaxf(aB + aj - ib, 1e-6f));
            }
            if (j2 < KK) {
                float4 bj = sb[j2];
                float aj = sa[j2];
                float x1a = fmaxf(bA.x, bj.x), y1a = fmaxf(bA.y, bj.y);
                float x2a = fminf(bA.z, bj.z), y2a = fminf(bA.w, bj.w);
                float ia = fmaxf(x2a - x1a, 0.0f) * fmaxf(y2a - y1a, 0.0f);
                sA2 = (j2 > i0) && (ia > 0.5f * fmaxf(aA + aj - ia, 1e-6f));
                float x1b = fmaxf(bB.x, bj.x), y1b = fmaxf(bB.y, bj.y);
                float x2b = fminf(bB.z, bj.z), y2b = fminf(bB.w, bj.w);
                float ib = fmaxf(x2b - x1b, 0.0f) * fmaxf(y2b - y1b, 0.0f);
                sB2 = (j2 > i1) && (ib > 0.5f * fmaxf(aB + aj - ib, 1e-6f));
            }
            unsigned bA1 = __ballot_sync(0xFFFFFFFFu, sA1);
            unsigned bA2 = __ballot_sync(0xFFFFFFFFu, sA2);
            unsigned bB1 = __ballot_sync(0xFFFFFFFFu, sB1);
            unsigned bB2 = __ballot_sync(0xFFFFFFFFu, sB2);
            if (lane == 0) {
                r0[w] = ((unsigned long long)bA2 << 32) | (unsigned long long)bA1;
                r1[w] = ((unsigned long long)bB2 << 32) | (unsigned long long)bB1;
            }
        }
    }
}

// ---------------- K4: sequential greedy reduction (depth-8 register-ring prefetch) ----------------
__global__ __launch_bounds__(32) void nms_reduce_kernel() {
    int bc = blockIdx.x;
    int lane = threadIdx.x;
    const unsigned long long* mrow = g_mask + (size_t)bc * KK * 16;
    unsigned long long removed = 0ull;
    unsigned long long pf[8];
#pragma unroll
    for (int s = 0; s < 8; s++)
        pf[s] = (lane < 16) ? mrow[(size_t)s * 16 + lane] : 0ull;
    int cnt = 0;
    for (int base = 0; base < KK; base += 8) {
#pragma unroll
        for (int s = 0; s < 8; s++) {
            int i = base + s;
            unsigned long long mm = pf[s];
            int nx = i + 8;
            pf[s] = (nx < KK && lane < 16) ? mrow[(size_t)nx * 16 + lane] : 0ull;
            int w0 = i >> 6;
            mm = (lane < w0) ? 0ull : mm;     // sanitize sub-diagonal words
            unsigned long long r = __shfl_sync(0xFFFFFFFFu, removed, w0);
            bool keep = !((r >> (i & 63)) & 1ull);
            if (keep) removed |= mm;
            if (lane == 0) {
                float v = g_topval[bc * KK + i];
                float outv = (keep && v > SCORE_T) ? v : 0.0f;
                g_val[bc * KK + i] = outv;
                if (outv > 0.0f) {
                    g_cval[bc * KK + cnt] = outv;   // survivors stay score-descending
                    g_cidx[bc * KK + cnt] = i;
                    cnt++;
                }
            }
        }
    }
    if (lane == 0) g_cnt[bc] = cnt;
}

// ---------------- K5: per-image top-100 over 9 classes ----------------
__global__ __launch_bounds__(512) void final_kernel(float* __restrict__ out) {
    int b = blockIdx.x;
    int tid = threadIdx.x;
    __shared__ unsigned long long arr[1024];
    for (int i = tid; i < 1024; i += 512) arr[i] = 0ull;
    __syncthreads();
    // only the top-100 of each class can reach the global top-100
    for (int s = tid; s < 900; s += 512) {
        int c = s / 100, r = s % 100;
        int bc = b * 9 + c;
        if (r < g_cnt[bc]) {
            float v = g_cval[bc * KK + r];
            int k = g_cidx[bc * KK + r];
            unsigned flat = (unsigned)(c * KK + k);
            arr[s] = ((unsigned long long)__float_as_uint(v) << 32) |
                     (unsigned long long)(0xFFFFFFFFu - flat);
        }
    }
    __syncthreads();
    for (int k = 2; k <= 1024; k <<= 1)
        for (int j = k >> 1; j > 0; j >>= 1) {
            __syncthreads();
            for (int i = tid; i < 1024; i += 512) {
                int ixj = i ^ j;
                if (ixj > i) {
                    unsigned long long a = arr[i], bv = arr[ixj];
                    if (((i & k) == 0) ? (a < bv) : (a > bv)) { arr[i] = bv; arr[ixj] = a; }
                }
            }
        }
    __syncthreads();

    float* o = out + (size_t)b * MAXDET * 6;
    if (tid < MAXDET) {
        unsigned long long v = arr[tid];
        if (v) {
            unsigned flat = 0xFFFFFFFFu - (unsigned)v;
            int c = flat / KK, k2 = flat % KK;
            float4 bx = g_topbox[(b * 9 + c) * KK + k2];
            float scv = __uint_as_float((unsigned)(v >> 32));
            o[tid * 6 + 0] = bx.x; o[tid * 6 + 1] = bx.y;
            o[tid * 6 + 2] = bx.z; o[tid * 6 + 3] = bx.w;
            o[tid * 6 + 4] = scv;  o[tid * 6 + 5] = (float)c;
        }
    }
    __syncthreads();
    // exact-tie fallback: < 100 positive detections -> zero-score entries by ascending flat idx
    if (tid == 0 && arr[MAXDET - 1] == 0ull) {
        int f = 0;
        for (int t = 0; t < MAXDET; t++) {
            if (arr[t]) continue;
            while (f < 9000 && g_val[(size_t)b * 9000 + f] != 0.0f) f++;
            int c = 0, k2 = 0;
            float4 bx = make_float4(0.f, 0.f, 0.f, 0.f);
            if (f < 9000) {
                c = f / KK; k2 = f % KK;
                bx = g_topbox[(b * 9 + c) * KK + k2];
                f++;
            }
            o[t * 6 + 0] = bx.x; o[t * 6 + 1] = bx.y;
            o[t * 6 + 2] = bx.z; o[t * 6 + 3] = bx.w;
            o[t * 6 + 4] = 0.0f; o[t * 6 + 5] = (float)c;
        }
    }
}

// ---------------- launch ----------------
extern "C" void kernel_launch(void* const* d_in, const int* in_sizes, int n_in,
                              void* d_out, int out_size) {
    (void)in_sizes; (void)n_in; (void)out_size;
    const float* anchors = (const float*)d_in[0];
    const float* deltas  = (const float*)d_in[1];
    const float* cls     = (const float*)d_in[2];
    const float* obj     = (const float*)d_in[3];
    float* out = (float*)d_out;

    score_kernel<<<dim3(NN / 256, BB), 256>>>(cls, obj);
    select_kernel<<<BC, 1024>>>((const float4*)anchors, (const float4*)deltas);
    nms_mask_kernel<<<dim3(BC, 4), 1024>>>();
    nms_reduce_kernel<<<BC, 32>>>();
    final_kernel<<<BB, 512>>>(out);
}

// round 4
// speedup vs baseline: 1.9115x; 1.1539x over previous
#include <cuda_runtime.h>
#include <cuda_bf16.h>
#include <cstdint>

#define NN 193536
#define BB 16
#define CC 9
#define KK 1000
#define BC 144            // BB*CC
#define MAXDET 100
#define SCORE_T 0.05f
#define IOU_T 0.5f

// keys are positive floats in (0.05, 1): 20-bit prefixes span [0x3D4CC, 0x3F7FF]
#define P_LO 0x3D4CCu
#define HB 9012
#define HBPAD 9024        // padded to 282*32
#define KT_MIN 0x3D4CCCCEu   // smallest uint key with float > 0.05f

// ---------------- scratch (static device globals; no dynamic alloc) ----------------
__device__ float              g_scores[(size_t)BC * NN];       // ~111.5 MB, [(b*9+c)][n]
__device__ float              g_topval[BC * KK];
__device__ float4             g_topbox[BC * KK];
__device__ unsigned long long g_mask[(size_t)BC * KK * 16];    // 18.4 MB suppression bitmatrix
__device__ float              g_val[BC * KK];                  // post-NMS score (0 for invalid)
__device__ float              g_cval[BC * KK];                 // compacted survivors (desc order)
__device__ int                g_cidx[BC * KK];
__device__ int                g_cnt[BC];

// ---------------- K1: sigmoid + transpose scores to class-major ----------------
__global__ __launch_bounds__(256) void score_kernel(const float* __restrict__ cls,
                                                    const float* __restrict__ obj) {
    int b = blockIdx.y;
    int n0 = blockIdx.x * 256;
    int tid = threadIdx.x;
    __shared__ float sh[256 * 9];
    const float* src = cls + ((size_t)b * NN + n0) * 9;
    for (int i = tid; i < 2304; i += 256) sh[i] = src[i];
    __syncthreads();
    int n = n0 + tid;
    float so = 1.0f / (1.0f + expf(-obj[(size_t)b * NN + n]));
#pragma unroll
    for (int c = 0; c < 9; c++) {
        float s = 1.0f / (1.0f + expf(-sh[tid * 9 + c]));
        g_scores[((size_t)(b * 9 + c)) * NN + n] = s * so;
    }
}

// ---------------- scan helper: boundary bin from top, given remaining need ----------------
__device__ __forceinline__ void scan_boundary(unsigned* hist, unsigned* gsum, int NG,
                                              int tid, int* sh_sel, int* sh_need,
                                              int* sh_take, unsigned* sh_gat) {
    if (tid < NG) {
        unsigned t = 0;
        int base = tid * 32;
#pragma unroll 8
        for (int i = 0; i < 32; i++) t += hist[base + i];
        gsum[tid] = t;
    }
    __syncthreads();
    if (tid == 0) {
        int need = *sh_need;
        unsigned acc = 0;
        int g = NG - 1;
        for (; g >= 0; g--) {
            if (acc + gsum[g] >= (unsigned)need) break;
            acc += gsum[g];
        }
        if (g < 0) {
            *sh_take = 1;  // fewer than `need` candidates total
        } else {
            int bin = g * 32 + 31;
            for (;; bin--) {
                if (acc + hist[bin] >= (unsigned)need) break;
                acc += hist[bin];
            }
            *sh_sel = bin;
            *sh_need = need - (int)acc;          // remaining need inside boundary bin
            *sh_gat = acc + hist[bin];           // total items with key >= bin prefix
        }
    }
    __syncthreads();
}

__device__ __forceinline__ void hist_add(unsigned* hist, int bin) {
    unsigned m = __match_any_sync(__activemask(), bin);
    int leader = __ffs(m) - 1;
    if ((threadIdx.x & 31) == leader) atomicAdd(&hist[bin], __popc(m));
}

// ---------------- K2: per-(b,c) exact top-1000 (1 hist pass + gather) + decode ----------------
__global__ __launch_bounds__(1024) void select_kernel(const float4* __restrict__ anchors,
                                                      const float4* __restrict__ deltas) {
    int bc = blockIdx.x;
    int tid = threadIdx.x;
    const float4* sc4 = (const float4*)(g_scores + (size_t)bc * NN);

    __shared__ __align__(16) unsigned char sraw[HBPAD * 4];   // 36 KB overlay
    unsigned* hist = (unsigned*)sraw;
    unsigned long long* arr = (unsigned long long*)sraw;      // 16 KB, overlays hist
    __shared__ unsigned gsum[288];
    __shared__ int sh_sel, sh_need, sh_take, sh_cnt;
    __shared__ unsigned sh_gat;

    // ---- pass A: histogram over 20-bit prefixes (monotone, low contention) ----
    for (int i = tid; i < HBPAD; i += 1024) hist[i] = 0;
    if (tid == 0) { sh_need = KK; sh_take = 0; }
    __syncthreads();
    for (int n4 = tid; n4 < NN / 4; n4 += 1024) {
        float4 v = sc4[n4];
        float sv[4] = {v.x, v.y, v.z, v.w};
#pragma unroll
        for (int c = 0; c < 4; c++) {
            float s = sv[c];
            if (s > SCORE_T) {
                int bin = (int)(__float_as_uint(s) >> 12) - (int)P_LO;
                bin = min(max(bin, 0), HB - 1);
                hist_add(hist, bin);
            }
        }
    }
    __syncthreads();
    scan_boundary(hist, gsum, 282, tid, &sh_sel, &sh_need, &sh_take, &sh_gat);

    unsigned Kt;
    if (sh_take) {
        Kt = KT_MIN;                       // fewer than 1000 total: take everything > thresh
    } else {
        unsigned prefix = P_LO + (unsigned)sh_sel;
        Kt = prefix << 12;
        if (sh_gat > 2048u) {
            // ---- rare refinement: low 12 bits within boundary prefix ----
            __syncthreads();
            for (int i = tid; i < 4096; i += 1024) hist[i] = 0;
            __syncthreads();
            for (int n4 = tid; n4 < NN / 4; n4 += 1024) {
                float4 v = sc4[n4];
                float sv[4] = {v.x, v.y, v.z, v.w};
#pragma unroll
                for (int c = 0; c < 4; c++) {
                    float s = sv[c];
                    if (s > SCORE_T) {
                        unsigned k = __float_as_uint(s);
                        if ((k >> 12) == prefix) hist_add(hist, (int)(k & 0xFFF));
                    }
                }
            }
            __syncthreads();
            scan_boundary(hist, gsum, 128, tid, &sh_sel, &sh_need, &sh_take, &sh_gat);
            Kt = (prefix << 12) | (unsigned)sh_sel;    // exact 32-bit threshold
        }
    }

    // ---- gather candidates with key >= Kt ----
    __syncthreads();
    for (int i = tid; i < 2048; i += 1024) arr[i] = 0ull;
    if (tid == 0) sh_cnt = 0;
    __syncthreads();
    for (int n4 = tid; n4 < NN / 4; n4 += 1024) {
        float4 v = sc4[n4];
        float sv[4] = {v.x, v.y, v.z, v.w};
#pragma unroll
        for (int c = 0; c < 4; c++) {
            float s = sv[c];
            if (s > SCORE_T) {
                unsigned k = __float_as_uint(s);
                if (k >= Kt) {
                    int p = atomicAdd(&sh_cnt, 1);
                    unsigned n = (unsigned)(n4 * 4 + c);
                    if (p < 2048)
                        arr[p] = ((unsigned long long)k << 32) |
                                 (unsigned long long)(0xFFFFFFFFu - n);
                }
            }
        }
    }
    __syncthreads();

    // ---- bitonic sort 2048 desc (score desc, idx asc on ties) ----
    for (int k = 2; k <= 2048; k <<= 1)
        for (int j = k >> 1; j > 0; j >>= 1) {
            __syncthreads();
            for (int i = tid; i < 2048; i += 1024) {
                int ixj = i ^ j;
                if (ixj > i) {
                    unsigned long long a = arr[i], b = arr[ixj];
                    if (((i & k) == 0) ? (a < b) : (a > b)) { arr[i] = b; arr[ixj] = a; }
                }
            }
        }
    __syncthreads();

    // ---- epilogue: write topval + decode box inline ----
    if (tid < KK) {
        unsigned long long v = arr[tid];
        float val;
        int idx;
        if (v) {
            val = __uint_as_float((unsigned)(v >> 32));
            idx = (int)(0xFFFFFFFFu - (unsigned)v);
        } else {
            val = -1.0f;    // padding; cannot surface in output
            idx = tid;
        }
        g_topval[bc * KK + tid] = val;
        int b = bc / CC;
        float4 an = anchors[idx];
        float4 dl = deltas[(size_t)b * NN + idx];
        float acx = (an.x + an.z) * 0.5f, acy = (an.y + an.w) * 0.5f;
        float aw = fmaxf(an.z - an.x, 1.0f), ah = fmaxf(an.w - an.y, 1.0f);
        float cx = dl.x * aw + acx, cy = dl.y * ah + acy;
        float w = expf(fminf(dl.z, 4.0f)) * aw;
        float h = expf(fminf(dl.w, 4.0f)) * ah;
        g_topbox[bc * KK + tid] = make_float4(cx - w * 0.5f, cy - h * 0.5f,
                                              cx + w * 0.5f, cy + h * 0.5f);
    }
}

// ---------------- K3: NMS suppression bitmatrix (row-pair per warp, ballot) ----------------
__global__ __launch_bounds__(1024) void nms_mask_kernel() {
    int bc = blockIdx.x;
    int tid = threadIdx.x;
    int lane = tid & 31;
    int wid = tid >> 5;
    __shared__ float4 sb[KK];
    __shared__ float sa[KK];
    for (int i = tid; i < KK; i += 1024) {
        float4 bx = g_topbox[bc * KK + i];
        sb[i] = bx;
        sa[i] = (bx.z - bx.x) * (bx.w - bx.y);
    }
    __syncthreads();
    int gw = blockIdx.y * 32 + wid;   // 0..127 global warp within bc
    for (int p = gw; p < KK / 2; p += 128) {
        int i0 = p * 2, i1 = i0 + 1;
        float4 bA = sb[i0], bB = sb[i1];
        float aA = sa[i0], aB = sa[i1];
        unsigned long long* r0 = &g_mask[((size_t)bc * KK + i0) * 16];
        unsigned long long* r1 = r0 + 16;
        for (int w = i0 >> 6; w < 16; w++) {
            int j1 = (w << 6) + lane;
            int j2 = j1 + 32;
            bool sA1 = false, sA2 = false, sB1 = false, sB2 = false;
            {
                float4 bj = sb[j1];
                float aj = sa[j1];
                float x1a = fmaxf(bA.x, bj.x), y1a = fmaxf(bA.y, bj.y);
                float x2a = fminf(bA.z, bj.z), y2a = fminf(bA.w, bj.w);
                float ia = fmaxf(x2a - x1a, 0.0f) * fmaxf(y2a - y1a, 0.0f);
                sA1 = (j1 > i0) && (j1 < KK) && (ia > 0.5f * fmaxf(aA + aj - ia, 1e-6f));
                float x1b = fmaxf(bB.x, bj.x), y1b = fmaxf(bB.y, bj.y);
                float x2b = fminf(bB.z, bj.z), y2b = fminf(bB.w, bj.w);
                float ib = fmaxf(x2b - x1b, 0.0f) * fmaxf(y2b - y1b, 0.0f);
                sB1 = (j1 > i1) && (j1 < KK) && (ib > 0.5f * fmaxf(aB + aj - ib, 1e-6f));
            }
            if (j2 < KK) {
                float4 bj = sb[j2];
                float aj = sa[j2];
                float x1a = fmaxf(bA.x, bj.x), y1a = fmaxf(bA.y, bj.y);
                float x2a = fminf(bA.z, bj.z), y2a = fminf(bA.w, bj.w);
                float ia = fmaxf(x2a - x1a, 0.0f) * fmaxf(y2a - y1a, 0.0f);
                sA2 = (j2 > i0) && (ia > 0.5f * fmaxf(aA + aj - ia, 1e-6f));
                float x1b = fmaxf(bB.x, bj.x), y1b = fmaxf(bB.y, bj.y);
                float x2b = fminf(bB.z, bj.z), y2b = fminf(bB.w, bj.w);
                float ib = fmaxf(x2b - x1b, 0.0f) * fmaxf(y2b - y1b, 0.0f);
                sB2 = (j2 > i1) && (ib > 0.5f * fmaxf(aB + aj - ib, 1e-6f));
            }
            unsigned bA1 = __ballot_sync(0xFFFFFFFFu, sA1);
            unsigned bA2 = __ballot_sync(0xFFFFFFFFu, sA2);
            unsigned bB1 = __ballot_sync(0xFFFFFFFFu, sB1);
            unsigned bB2 = __ballot_sync(0xFFFFFFFFu, sB2);
            if (lane == 0) {
                r0[w] = ((unsigned long long)bA2 << 32) | (unsigned long long)bA1;
                r1[w] = ((unsigned long long)bB2 << 32) | (unsigned long long)bB1;
            }
        }
    }
}

// ---------------- K4: sequential greedy reduction ----------------
// Critical path is ONLY shfl -> bit test -> predicated OR. Keep decisions are
// recorded in registers (lane i>>5 holds bit i&31); all score loads and the
// survivor compaction happen in a parallel epilogue.
__global__ __launch_bounds__(32) void nms_reduce_kernel() {
    int bc = blockIdx.x;
    int lane = threadIdx.x;
    const unsigned long long* mrow = g_mask + (size_t)bc * KK * 16;
    unsigned long long removed = 0ull;
    unsigned keepbits = 0u;
    unsigned long long pf[8];
#pragma unroll
    for (int s = 0; s < 8; s++)
        pf[s] = (lane < 16) ? mrow[(size_t)s * 16 + lane] : 0ull;
    for (int base = 0; base < KK; base += 8) {
#pragma unroll
        for (int s = 0; s < 8; s++) {
            int i = base + s;
            unsigned long long mm = pf[s];
            int nx = i + 8;
            pf[s] = (nx < KK && lane < 16) ? mrow[(size_t)nx * 16 + lane] : 0ull;
            int w0 = i >> 6;
            mm = (lane < w0) ? 0ull : mm;     // sanitize sub-diagonal words
            unsigned long long r = __shfl_sync(0xFFFFFFFFu, removed, w0);
            bool keep = !((r >> (i & 63)) & 1ull);
            if (keep) {
                removed |= mm;
                if (lane == (i >> 5)) keepbits |= 1u << (i & 31);
            }
        }
    }
    // ---- parallel epilogue: apply score threshold, write g_val, compact survivors ----
    int cnt = 0;
    for (int w = 0; w < 32; w++) {
        unsigned kb = __shfl_sync(0xFFFFFFFFu, keepbits, w);
        int i = w * 32 + lane;
        float v = (i < KK) ? g_topval[bc * KK + i] : -1.0f;
        bool valid = (i < KK) && ((kb >> lane) & 1u) && (v > SCORE_T);
        if (i < KK) g_val[bc * KK + i] = valid ? v : 0.0f;
        unsigned bal = __ballot_sync(0xFFFFFFFFu, valid);
        int pos = cnt + __popc(bal & ((1u << lane) - 1u));
        if (valid) {
            g_cval[bc * KK + pos] = v;      // survivors stay score-descending
            g_cidx[bc * KK + pos] = i;
        }
        cnt += __popc(bal);
    }
    if (lane == 0) g_cnt[bc] = cnt;
}

// ---------------- K5: per-image top-100 over 9 classes ----------------
__global__ __launch_bounds__(512) void final_kernel(float* __restrict__ out) {
    int b = blockIdx.x;
    int tid = threadIdx.x;
    __shared__ unsigned long long arr[1024];
    for (int i = tid; i < 1024; i += 512) arr[i] = 0ull;
    __syncthreads();
    // only the top-100 of each class can reach the global top-100
    for (int s = tid; s < 900; s += 512) {
        int c = s / 100, r = s % 100;
        int bc = b * 9 + c;
        if (r < g_cnt[bc]) {
            float v = g_cval[bc * KK + r];
            int k = g_cidx[bc * KK + r];
            unsigned flat = (unsigned)(c * KK + k);
            arr[s] = ((unsigned long long)__float_as_uint(v) << 32) |
                     (unsigned long long)(0xFFFFFFFFu - flat);
        }
    }
    __syncthreads();
    for (int k = 2; k <= 1024; k <<= 1)
        for (int j = k >> 1; j > 0; j >>= 1) {
            __syncthreads();
            for (int i = tid; i < 1024; i += 512) {
                int ixj = i ^ j;
                if (ixj > i) {
                    unsigned long long a = arr[i], bv = arr[ixj];
                    if (((i & k) == 0) ? (a < bv) : (a > bv)) { arr[i] = bv; arr[ixj] = a; }
                }
            }
        }
    __syncthreads();

    float* o = out + (size_t)b * MAXDET * 6;
    if (tid < MAXDET) {
        unsigned long long v = arr[tid];
        if (v) {
            unsigned flat = 0xFFFFFFFFu - (unsigned)v;
            int c = flat / KK, k2 = flat % KK;
            float4 bx = g_topbox[(b * 9 + c) * KK + k2];
            float scv = __uint_as_float((unsigned)(v >> 32));
            o[tid * 6 + 0] = bx.x; o[tid * 6 + 1] = bx.y;
            o[tid * 6 + 2] = bx.z; o[tid * 6 + 3] = bx.w;
            o[tid * 6 + 4] = scv;  o[tid * 6 + 5] = (float)c;
        }
    }
    __syncthreads();
    // exact-tie fallback: < 100 positive detections -> zero-score entries by ascending flat idx
    if (tid == 0 && arr[MAXDET - 1] == 0ull) {
        int f = 0;
        for (int t = 0; t < MAXDET; t++) {
            if (arr[t]) continue;
            while (f < 9000 && g_val[(size_t)b * 9000 + f] != 0.0f) f++;
            int c = 0, k2 = 0;
            float4 bx = make_float4(0.f, 0.f, 0.f, 0.f);
            if (f < 9000) {
                c = f / KK; k2 = f % KK;
                bx = g_topbox[(b * 9 + c) * KK + k2];
                f++;
            }
            o[t * 6 + 0] = bx.x; o[t * 6 + 1] = bx.y;
            o[t * 6 + 2] = bx.z; o[t * 6 + 3] = bx.w;
            o[t * 6 + 4] = 0.0f; o[t * 6 + 5] = (float)c;
        }
    }
}

// ---------------- launch ----------------
extern "C" void kernel_launch(void* const* d_in, const int* in_sizes, int n_in,
                              void* d_out, int out_size) {
    (void)in_sizes; (void)n_in; (void)out_size;
    const float* anchors = (const float*)d_in[0];
    const float* deltas  = (const float*)d_in[1];
    const float* cls     = (const float*)d_in[2];
    const float* obj     = (const float*)d_in[3];
    float* out = (float*)d_out;

    score_kernel<<<dim3(NN / 256, BB), 256>>>(cls, obj);
    select_kernel<<<BC, 1024>>>((const float4*)anchors, (const float4*)deltas);
    nms_mask_kernel<<<dim3(BC, 4), 1024>>>();
    nms_reduce_kernel<<<BC, 32>>>();
    final_kernel<<<BB, 512>>>(out);
}

// round 5
// speedup vs baseline: 2.0643x; 1.0799x over previous
#include <cuda_runtime.h>
#include <cuda_bf16.h>
#include <cstdint>

#define NN 193536
#define BB 16
#define CC 9
#define KK 1000
#define BC 144            // BB*CC
#define MAXDET 100
#define SCORE_T 0.05f
#define IOU_T 0.5f

// keys are positive floats in (0.05, 1): 20-bit prefixes span [0x3D4CC, 0x3F7FF]
#define P_LO 0x3D4CCu
#define HB 9012
#define HBPAD 9024        // padded to 282*32
#define KT_MIN 0x3D4CCCCEu   // smallest uint key with float > 0.05f

// ---------------- scratch (static device globals; no dynamic alloc) ----------------
__device__ float              g_scores[(size_t)BC * NN];       // ~111.5 MB, [(b*9+c)][n]
__device__ float              g_topval[BC * KK];
__device__ float4             g_topbox[BC * KK];
__device__ unsigned long long g_mask[(size_t)BC * KK * 16];    // 18.4 MB suppression bitmatrix
__device__ float              g_val[BC * KK];                  // post-NMS score (0 for invalid)
__device__ float              g_cval[BC * KK];                 // compacted survivors (desc order)
__device__ int                g_cidx[BC * KK];
__device__ int                g_cnt[BC];

// ---------------- K1: sigmoid + transpose scores to class-major ----------------
__global__ __launch_bounds__(256) void score_kernel(const float* __restrict__ cls,
                                                    const float* __restrict__ obj) {
    int b = blockIdx.y;
    int n0 = blockIdx.x * 256;
    int tid = threadIdx.x;
    __shared__ float sh[256 * 9];
    const float* src = cls + ((size_t)b * NN + n0) * 9;
    for (int i = tid; i < 2304; i += 256) sh[i] = src[i];
    __syncthreads();
    int n = n0 + tid;
    float so = 1.0f / (1.0f + expf(-obj[(size_t)b * NN + n]));
#pragma unroll
    for (int c = 0; c < 9; c++) {
        float s = 1.0f / (1.0f + expf(-sh[tid * 9 + c]));
        g_scores[((size_t)(b * 9 + c)) * NN + n] = s * so;
    }
}

// ---------------- scan helper: boundary bin from top, given remaining need ----------------
__device__ __forceinline__ void scan_boundary(unsigned* hist, unsigned* gsum, int NG,
                                              int tid, int* sh_sel, int* sh_need,
                                              int* sh_take, unsigned* sh_gat) {
    if (tid < NG) {
        unsigned t = 0;
        int base = tid * 32;
#pragma unroll 8
        for (int i = 0; i < 32; i++) t += hist[base + i];
        gsum[tid] = t;
    }
    __syncthreads();
    if (tid == 0) {
        int need = *sh_need;
        unsigned acc = 0;
        int g = NG - 1;
        for (; g >= 0; g--) {
            if (acc + gsum[g] >= (unsigned)need) break;
            acc += gsum[g];
        }
        if (g < 0) {
            *sh_take = 1;  // fewer than `need` candidates total
        } else {
            int bin = g * 32 + 31;
            for (;; bin--) {
                if (acc + hist[bin] >= (unsigned)need) break;
                acc += hist[bin];
            }
            *sh_sel = bin;
            *sh_need = need - (int)acc;          // remaining need inside boundary bin
            *sh_gat = acc + hist[bin];           // total items with key >= bin prefix
        }
    }
    __syncthreads();
}

__device__ __forceinline__ void hist_add(unsigned* hist, int bin) {
    unsigned m = __match_any_sync(__activemask(), bin);
    int leader = __ffs(m) - 1;
    if ((threadIdx.x & 31) == leader) atomicAdd(&hist[bin], __popc(m));
}

// ---------------- K2: per-(b,c) exact top-1000 (1 hist pass + gather) + decode ----------------
__global__ __launch_bounds__(1024) void select_kernel(const float4* __restrict__ anchors,
                                                      const float4* __restrict__ deltas) {
    int bc = blockIdx.x;
    int tid = threadIdx.x;
    const float4* sc4 = (const float4*)(g_scores + (size_t)bc * NN);

    __shared__ __align__(16) unsigned char sraw[HBPAD * 4];   // 36 KB overlay
    unsigned* hist = (unsigned*)sraw;
    unsigned long long* arr = (unsigned long long*)sraw;      // 16 KB, overlays hist
    __shared__ unsigned gsum[288];
    __shared__ int sh_sel, sh_need, sh_take, sh_cnt;
    __shared__ unsigned sh_gat;

    // ---- pass A: histogram over 20-bit prefixes (monotone, low contention) ----
    for (int i = tid; i < HBPAD; i += 1024) hist[i] = 0;
    if (tid == 0) { sh_need = KK; sh_take = 0; }
    __syncthreads();
    for (int n4 = tid; n4 < NN / 4; n4 += 1024) {
        float4 v = sc4[n4];
        float sv[4] = {v.x, v.y, v.z, v.w};
#pragma unroll
        for (int c = 0; c < 4; c++) {
            float s = sv[c];
            if (s > SCORE_T) {
                int bin = (int)(__float_as_uint(s) >> 12) - (int)P_LO;
                bin = min(max(bin, 0), HB - 1);
                hist_add(hist, bin);
            }
        }
    }
    __syncthreads();
    scan_boundary(hist, gsum, 282, tid, &sh_sel, &sh_need, &sh_take, &sh_gat);

    unsigned Kt;
    if (sh_take) {
        Kt = KT_MIN;                       // fewer than 1000 total: take everything > thresh
    } else {
        unsigned prefix = P_LO + (unsigned)sh_sel;
        Kt = prefix << 12;
        if (sh_gat > 2048u) {
            // ---- rare refinement: low 12 bits within boundary prefix ----
            __syncthreads();
            for (int i = tid; i < 4096; i += 1024) hist[i] = 0;
            __syncthreads();
            for (int n4 = tid; n4 < NN / 4; n4 += 1024) {
                float4 v = sc4[n4];
                float sv[4] = {v.x, v.y, v.z, v.w};
#pragma unroll
                for (int c = 0; c < 4; c++) {
                    float s = sv[c];
                    if (s > SCORE_T) {
                        unsigned k = __float_as_uint(s);
                        if ((k >> 12) == prefix) hist_add(hist, (int)(k & 0xFFF));
                    }
                }
            }
            __syncthreads();
            scan_boundary(hist, gsum, 128, tid, &sh_sel, &sh_need, &sh_take, &sh_gat);
            Kt = (prefix << 12) | (unsigned)sh_sel;    // exact 32-bit threshold
        }
    }

    // ---- gather candidates with key >= Kt ----
    __syncthreads();
    for (int i = tid; i < 2048; i += 1024) arr[i] = 0ull;
    if (tid == 0) sh_cnt = 0;
    __syncthreads();
    for (int n4 = tid; n4 < NN / 4; n4 += 1024) {
        float4 v = sc4[n4];
        float sv[4] = {v.x, v.y, v.z, v.w};
#pragma unroll
        for (int c = 0; c < 4; c++) {
            float s = sv[c];
            if (s > SCORE_T) {
                unsigned k = __float_as_uint(s);
                if (k >= Kt) {
                    int p = atomicAdd(&sh_cnt, 1);
                    unsigned n = (unsigned)(n4 * 4 + c);
                    if (p < 2048)
                        arr[p] = ((unsigned long long)k << 32) |
                                 (unsigned long long)(0xFFFFFFFFu - n);
                }
            }
        }
    }
    __syncthreads();

    // ---- bitonic sort 2048 desc (score desc, idx asc on ties) ----
    for (int k = 2; k <= 2048; k <<= 1)
        for (int j = k >> 1; j > 0; j >>= 1) {
            __syncthreads();
            for (int i = tid; i < 2048; i += 1024) {
                int ixj = i ^ j;
                if (ixj > i) {
                    unsigned long long a = arr[i], b = arr[ixj];
                    if (((i & k) == 0) ? (a < b) : (a > b)) { arr[i] = b; arr[ixj] = a; }
                }
            }
        }
    __syncthreads();

    // ---- epilogue: write topval + decode box inline ----
    if (tid < KK) {
        unsigned long long v = arr[tid];
        float val;
        int idx;
        if (v) {
            val = __uint_as_float((unsigned)(v >> 32));
            idx = (int)(0xFFFFFFFFu - (unsigned)v);
        } else {
            val = -1.0f;    // padding; cannot surface in output
            idx = tid;
        }
        g_topval[bc * KK + tid] = val;
        int b = bc / CC;
        float4 an = anchors[idx];
        float4 dl = deltas[(size_t)b * NN + idx];
        float acx = (an.x + an.z) * 0.5f, acy = (an.y + an.w) * 0.5f;
        float aw = fmaxf(an.z - an.x, 1.0f), ah = fmaxf(an.w - an.y, 1.0f);
        float cx = dl.x * aw + acx, cy = dl.y * ah + acy;
        float w = expf(fminf(dl.z, 4.0f)) * aw;
        float h = expf(fminf(dl.w, 4.0f)) * ah;
        g_topbox[bc * KK + tid] = make_float4(cx - w * 0.5f, cy - h * 0.5f,
                                              cx + w * 0.5f, cy + h * 0.5f);
    }
}

// ---------------- K3: NMS suppression bitmatrix (row-pair per warp, ballot) ----------------
__global__ __launch_bounds__(1024) void nms_mask_kernel() {
    int bc = blockIdx.x;
    int tid = threadIdx.x;
    int lane = tid & 31;
    int wid = tid >> 5;
    __shared__ float4 sb[KK];
    __shared__ float sa[KK];
    for (int i = tid; i < KK; i += 1024) {
        float4 bx = g_topbox[bc * KK + i];
        sb[i] = bx;
        sa[i] = (bx.z - bx.x) * (bx.w - bx.y);
    }
    __syncthreads();
    int gw = blockIdx.y * 32 + wid;   // 0..127 global warp within bc
    for (int p = gw; p < KK / 2; p += 128) {
        int i0 = p * 2, i1 = i0 + 1;
        float4 bA = sb[i0], bB = sb[i1];
        float aA = sa[i0], aB = sa[i1];
        unsigned long long* r0 = &g_mask[((size_t)bc * KK + i0) * 16];
        unsigned long long* r1 = r0 + 16;
        for (int w = i0 >> 6; w < 16; w++) {
            int j1 = (w << 6) + lane;
            int j2 = j1 + 32;
            bool sA1 = false, sA2 = false, sB1 = false, sB2 = false;
            {
                float4 bj = sb[j1];
                float aj = sa[j1];
                float x1a = fmaxf(bA.x, bj.x), y1a = fmaxf(bA.y, bj.y);
                float x2a = fminf(bA.z, bj.z), y2a = fminf(bA.w, bj.w);
                float ia = fmaxf(x2a - x1a, 0.0f) * fmaxf(y2a - y1a, 0.0f);
                sA1 = (j1 > i0) && (j1 < KK) && (ia > 0.5f * fmaxf(aA + aj - ia, 1e-6f));
                float x1b = fmaxf(bB.x, bj.x), y1b = fmaxf(bB.y, bj.y);
                float x2b = fminf(bB.z, bj.z), y2b = fminf(bB.w, bj.w);
                float ib = fmaxf(x2b - x1b, 0.0f) * fmaxf(y2b - y1b, 0.0f);
                sB1 = (j1 > i1) && (j1 < KK) && (ib > 0.5f * fmaxf(aB + aj - ib, 1e-6f));
            }
            if (j2 < KK) {
                float4 bj = sb[j2];
                float aj = sa[j2];
                float x1a = fmaxf(bA.x, bj.x), y1a = fmaxf(bA.y, bj.y);
                float x2a = fminf(bA.z, bj.z), y2a = fminf(bA.w, bj.w);
                float ia = fmaxf(x2a - x1a, 0.0f) * fmaxf(y2a - y1a, 0.0f);
                sA2 = (j2 > i0) && (ia > 0.5f * fmaxf(aA + aj - ia, 1e-6f));
                float x1b = fmaxf(bB.x, bj.x), y1b = fmaxf(bB.y, bj.y);
                float x2b = fminf(bB.z, bj.z), y2b = fminf(bB.w, bj.w);
                float ib = fmaxf(x2b - x1b, 0.0f) * fmaxf(y2b - y1b, 0.0f);
                sB2 = (j2 > i1) && (ib > 0.5f * fmaxf(aB + aj - ib, 1e-6f));
            }
            unsigned bA1 = __ballot_sync(0xFFFFFFFFu, sA1);
            unsigned bA2 = __ballot_sync(0xFFFFFFFFu, sA2);
            unsigned bB1 = __ballot_sync(0xFFFFFFFFu, sB1);
            unsigned bB2 = __ballot_sync(0xFFFFFFFFu, sB2);
            if (lane == 0) {
                r0[w] = ((unsigned long long)bA2 << 32) | (unsigned long long)bA1;
                r1[w] = ((unsigned long long)bB2 << 32) | (unsigned long long)bB1;
            }
        }
    }
}

// ---------------- K4: sequential greedy reduction (branchless chain, depth-16 ring) ----------------
__global__ __launch_bounds__(32) void nms_reduce_kernel() {
    int bc = blockIdx.x;
    int lane = threadIdx.x;
    const unsigned long long* mrow = g_mask + (size_t)bc * KK * 16;
    bool act = lane < 16;
    unsigned long long removed = 0ull;
    unsigned keepbits = 0u;
    unsigned long long pf[16];
#pragma unroll
    for (int s = 0; s < 16; s++)
        pf[s] = act ? mrow[(size_t)s * 16 + lane] : 0ull;

    // 62 full chunks of 16 (rows 0..991), then 8-row tail (992..999).
    for (int base = 0; base < 992; base += 16) {
#pragma unroll
        for (int s = 0; s < 16; s++) {
            int i = base + s;
            unsigned long long mm = pf[s];
            int nx = i + 16;
            pf[s] = (nx < KK && act) ? mrow[(size_t)nx * 16 + lane] : 0ull;
            int w0 = i >> 6;
            mm = (lane < w0) ? 0ull : mm;     // sanitize sub-diagonal words
            unsigned long long r = __shfl_sync(0xFFFFFFFFu, removed, w0);
            unsigned long long live = ((r >> (i & 63)) & 1ull) - 1ull;  // ~0ull if kept
            removed |= mm & live;
            keepbits |= (lane == (i >> 5)) ? ((unsigned)live & (1u << (i & 31))) : 0u;
        }
    }
#pragma unroll
    for (int s = 0; s < 8; s++) {
        int i = 992 + s;
        unsigned long long mm = pf[s];
        int w0 = i >> 6;
        mm = (lane < w0) ? 0ull : mm;
        unsigned long long r = __shfl_sync(0xFFFFFFFFu, removed, w0);
        unsigned long long live = ((r >> (i & 63)) & 1ull) - 1ull;
        removed |= mm & live;
        keepbits |= (lane == (i >> 5)) ? ((unsigned)live & (1u << (i & 31))) : 0u;
    }

    // ---- parallel epilogue: apply score threshold, write g_val, compact survivors ----
    int cnt = 0;
    for (int w = 0; w < 32; w++) {
        unsigned kb = __shfl_sync(0xFFFFFFFFu, keepbits, w);
        int i = w * 32 + lane;
        float v = (i < KK) ? g_topval[bc * KK + i] : -1.0f;
        bool valid = (i < KK) && ((kb >> lane) & 1u) && (v > SCORE_T);
        if (i < KK) g_val[bc * KK + i] = valid ? v : 0.0f;
        unsigned bal = __ballot_sync(0xFFFFFFFFu, valid);
        int pos = cnt + __popc(bal & ((1u << lane) - 1u));
        if (valid) {
            g_cval[bc * KK + pos] = v;      // survivors stay score-descending
            g_cidx[bc * KK + pos] = i;
        }
        cnt += __popc(bal);
    }
    if (lane == 0) g_cnt[bc] = cnt;
}

// ---------------- K5: per-image top-100 over 9 classes ----------------
__global__ __launch_bounds__(512) void final_kernel(float* __restrict__ out) {
    int b = blockIdx.x;
    int tid = threadIdx.x;
    __shared__ unsigned long long arr[1024];
    for (int i = tid; i < 1024; i += 512) arr[i] = 0ull;
    __syncthreads();
    // only the top-100 of each class can reach the global top-100
    for (int s = tid; s < 900; s += 512) {
        int c = s / 100, r = s % 100;
        int bc = b * 9 + c;
        if (r < g_cnt[bc]) {
            float v = g_cval[bc * KK + r];
            int k = g_cidx[bc * KK + r];
            unsigned flat = (unsigned)(c * KK + k);
            arr[s] = ((unsigned long long)__float_as_uint(v) << 32) |
                     (unsigned long long)(0xFFFFFFFFu - flat);
        }
    }
    __syncthreads();
    for (int k = 2; k <= 1024; k <<= 1)
        for (int j = k >> 1; j > 0; j >>= 1) {
            __syncthreads();
            for (int i = tid; i < 1024; i += 512) {
                int ixj = i ^ j;
                if (ixj > i) {
                    unsigned long long a = arr[i], bv = arr[ixj];
                    if (((i & k) == 0) ? (a < bv) : (a > bv)) { arr[i] = bv; arr[ixj] = a; }
                }
            }
        }
    __syncthreads();

    float* o = out + (size_t)b * MAXDET * 6;
    if (tid < MAXDET) {
        unsigned long long v = arr[tid];
        if (v) {
            unsigned flat = 0xFFFFFFFFu - (unsigned)v;
            int c = flat / KK, k2 = flat % KK;
            float4 bx = g_topbox[(b * 9 + c) * KK + k2];
            float scv = __uint_as_float((unsigned)(v >> 32));
            o[tid * 6 + 0] = bx.x; o[tid * 6 + 1] = bx.y;
            o[tid * 6 + 2] = bx.z; o[tid * 6 + 3] = bx.w;
            o[tid * 6 + 4] = scv;  o[tid * 6 + 5] = (float)c;
        }
    }
    __syncthreads();
    // exact-tie fallback: < 100 positive detections -> zero-score entries by ascending flat idx
    if (tid == 0 && arr[MAXDET - 1] == 0ull) {
        int f = 0;
        for (int t = 0; t < MAXDET; t++) {
            if (arr[t]) continue;
            while (f < 9000 && g_val[(size_t)b * 9000 + f] != 0.0f) f++;
            int c = 0, k2 = 0;
            float4 bx = make_float4(0.f, 0.f, 0.f, 0.f);
            if (f < 9000) {
                c = f / KK; k2 = f % KK;
                bx = g_topbox[(b * 9 + c) * KK + k2];
                f++;
            }
            o[t * 6 + 0] = bx.x; o[t * 6 + 1] = bx.y;
            o[t * 6 + 2] = bx.z; o[t * 6 + 3] = bx.w;
            o[t * 6 + 4] = 0.0f; o[t * 6 + 5] = (float)c;
        }
    }
}

// ---------------- launch ----------------
extern "C" void kernel_launch(void* const* d_in, const int* in_sizes, int n_in,
                              void* d_out, int out_size) {
    (void)in_sizes; (void)n_in; (void)out_size;
    const float* anchors = (const float*)d_in[0];
    const float* deltas  = (const float*)d_in[1];
    const float* cls     = (const float*)d_in[2];
    const float* obj     = (const float*)d_in[3];
    float* out = (float*)d_out;

    score_kernel<<<dim3(NN / 256, BB), 256>>>(cls, obj);
    select_kernel<<<BC, 1024>>>((const float4*)anchors, (const float4*)deltas);
    nms_mask_kernel<<<dim3(BC, 4), 1024>>>();
    nms_reduce_kernel<<<BC, 32>>>();
    final_kernel<<<BB, 512>>>(out);
}

// round 6
// speedup vs baseline: 3.2773x; 1.5876x over previous
#include <cuda_runtime.h>
#include <cuda_bf16.h>
#include <cstdint>

#define NN 193536
#define BB 16
#define CC 9
#define KK 1000
#define BC 144            // BB*CC
#define MAXDET 100
#define SCORE_T 0.05f
#define IOU_T 0.5f

// keys are positive floats in (0.05, 1): 20-bit prefixes span [0x3D4CC, 0x3F7FF]
#define P_LO 0x3D4CCu
#define HB 9012
#define HBPAD 9024        // padded to 282*32
#define KT_MIN 0x3D4CCCCEu   // smallest uint key with float > 0.05f

// ---------------- scratch (static device globals; no dynamic alloc) ----------------
__device__ float    g_scores[(size_t)BC * NN];       // ~111.5 MB, [(b*9+c)][n]
__device__ float    g_topval[BC * KK];
__device__ float4   g_topbox[BC * KK];
__device__ unsigned g_mask32[(size_t)BC * KK * 32];  // 18.4 MB suppression bitmatrix (u32 words)
__device__ float    g_val[BC * KK];                  // post-NMS score (0 for invalid)
__device__ float    g_cval[BC * KK];                 // compacted survivors (desc order)
__device__ int      g_cidx[BC * KK];
__device__ int      g_cnt[BC];

// ---------------- K1: sigmoid + transpose scores to class-major ----------------
__global__ __launch_bounds__(256) void score_kernel(const float* __restrict__ cls,
                                                    const float* __restrict__ obj) {
    int b = blockIdx.y;
    int n0 = blockIdx.x * 256;
    int tid = threadIdx.x;
    __shared__ float sh[256 * 9];
    const float* src = cls + ((size_t)b * NN + n0) * 9;
    for (int i = tid; i < 2304; i += 256) sh[i] = src[i];
    __syncthreads();
    int n = n0 + tid;
    float so = 1.0f / (1.0f + expf(-obj[(size_t)b * NN + n]));
#pragma unroll
    for (int c = 0; c < 9; c++) {
        float s = 1.0f / (1.0f + expf(-sh[tid * 9 + c]));
        g_scores[((size_t)(b * 9 + c)) * NN + n] = s * so;
    }
}

// ---------------- scan helper: boundary bin from top, given remaining need ----------------
__device__ __forceinline__ void scan_boundary(unsigned* hist, unsigned* gsum, int NG,
                                              int tid, int* sh_sel, int* sh_need,
                                              int* sh_take, unsigned* sh_gat) {
    if (tid < NG) {
        unsigned t = 0;
        int base = tid * 32;
#pragma unroll 8
        for (int i = 0; i < 32; i++) t += hist[base + i];
        gsum[tid] = t;
    }
    __syncthreads();
    if (tid == 0) {
        int need = *sh_need;
        unsigned acc = 0;
        int g = NG - 1;
        for (; g >= 0; g--) {
            if (acc + gsum[g] >= (unsigned)need) break;
            acc += gsum[g];
        }
        if (g < 0) {
            *sh_take = 1;  // fewer than `need` candidates total
        } else {
            int bin = g * 32 + 31;
            for (;; bin--) {
                if (acc + hist[bin] >= (unsigned)need) break;
                acc += hist[bin];
            }
            *sh_sel = bin;
            *sh_need = need - (int)acc;          // remaining need inside boundary bin
            *sh_gat = acc + hist[bin];           // total items with key >= bin prefix
        }
    }
    __syncthreads();
}

// ---------------- K2: per-(b,c) exact top-1000 (sample-guided hist) + decode ----------------
__global__ __launch_bounds__(1024) void select_kernel(const float4* __restrict__ anchors,
                                                      const float4* __restrict__ deltas) {
    int bc = blockIdx.x;
    int tid = threadIdx.x;
    const float* sc = g_scores + (size_t)bc * NN;
    const float4* sc4 = (const float4*)sc;

    __shared__ __align__(16) unsigned char sraw[HBPAD * 4];   // 36 KB overlay
    unsigned* hist = (unsigned*)sraw;
    unsigned* samp = (unsigned*)sraw;                         // 8 KB sample buffer
    unsigned long long* arr = (unsigned long long*)sraw;      // 16 KB gather/sort buffer
    __shared__ unsigned gsum[288];
    __shared__ int sh_sel, sh_need, sh_take, sh_cnt;
    __shared__ unsigned sh_gat, sh_T;

    // ---- phase 0: sample 2048 values, sort desc, take 32nd as conservative threshold ----
    for (int i = tid; i < 2048; i += 1024) {
        float s = sc[i * 94];
        samp[i] = (s > SCORE_T) ? __float_as_uint(s) : 0u;
    }
    __syncthreads();
    for (int k = 2; k <= 2048; k <<= 1)
        for (int j = k >> 1; j > 0; j >>= 1) {
            __syncthreads();
            for (int i = tid; i < 2048; i += 1024) {
                int ixj = i ^ j;
                if (ixj > i) {
                    unsigned a = samp[i], b = samp[ixj];
                    if (((i & k) == 0) ? (a < b) : (a > b)) { samp[i] = b; samp[ixj] = a; }
                }
            }
        }
    __syncthreads();
    if (tid == 0) {
        unsigned t = samp[31];                 // 32nd largest sample (expected full rank ~3000)
        sh_T = (t >= KT_MIN) ? t : KT_MIN;
    }
    __syncthreads();
    unsigned T = sh_T;

    // ---- phase 1: histogram over 20-bit prefixes, only keys >= T (few atomics) ----
    for (int attempt = 0; attempt < 2; attempt++) {
        __syncthreads();
        for (int i = tid; i < HBPAD; i += 1024) hist[i] = 0;
        if (tid == 0) { sh_need = KK; sh_take = 0; }
        __syncthreads();
        for (int n4 = tid; n4 < NN / 4; n4 += 1024) {
            float4 v = sc4[n4];
            float sv[4] = {v.x, v.y, v.z, v.w};
#pragma unroll
            for (int c = 0; c < 4; c++) {
                float s = sv[c];
                if (s > SCORE_T) {
                    unsigned k = __float_as_uint(s);
                    if (k >= T) {
                        int bin = (int)(k >> 12) - (int)P_LO;
                        bin = min(max(bin, 0), HB - 1);
                        atomicAdd(&hist[bin], 1u);
                    }
                }
            }
        }
        __syncthreads();
        scan_boundary(hist, gsum, 282, tid, &sh_sel, &sh_need, &sh_take, &sh_gat);
        if (!sh_take || T == KT_MIN) break;    // success, or genuinely <1000 total
        T = KT_MIN;                            // sample threshold too high: full rehist
    }

    unsigned Kt;
    if (sh_take) {
        Kt = KT_MIN;                           // fewer than 1000 total: take everything > thresh
    } else {
        unsigned prefix = P_LO + (unsigned)sh_sel;
        unsigned binlo = prefix << 12;
        Kt = (binlo < T) ? T : binlo;          // boundary bin may be T's own bin
        if (sh_gat > 2048u) {
            // ---- rare refinement: low 12 bits within boundary prefix (exact key bins) ----
            __syncthreads();
            for (int i = tid; i < 4096; i += 1024) hist[i] = 0;
            __syncthreads();
            for (int n4 = tid; n4 < NN / 4; n4 += 1024) {
                float4 v = sc4[n4];
                float sv[4] = {v.x, v.y, v.z, v.w};
#pragma unroll
                for (int c = 0; c < 4; c++) {
                    float s = sv[c];
                    if (s > SCORE_T) {
                        unsigned k = __float_as_uint(s);
                        if (k >= T && (k >> 12) == prefix) atomicAdd(&hist[k & 0xFFF], 1u);
                    }
                }
            }
            __syncthreads();
            scan_boundary(hist, gsum, 128, tid, &sh_sel, &sh_need, &sh_take, &sh_gat);
            Kt = (prefix << 12) | (unsigned)sh_sel;   // exact 32-bit threshold (>= T)
        }
    }

    // ---- phase 2: gather candidates with key >= Kt ----
    __syncthreads();
    for (int i = tid; i < 2048; i += 1024) arr[i] = 0ull;
    if (tid == 0) sh_cnt = 0;
    __syncthreads();
    for (int n4 = tid; n4 < NN / 4; n4 += 1024) {
        float4 v = sc4[n4];
        float sv[4] = {v.x, v.y, v.z, v.w};
#pragma unroll
        for (int c = 0; c < 4; c++) {
            float s = sv[c];
            if (s > SCORE_T) {
                unsigned k = __float_as_uint(s);
                if (k >= Kt) {
                    int p = atomicAdd(&sh_cnt, 1);
                    unsigned n = (unsigned)(n4 * 4 + c);
                    if (p < 2048)
                        arr[p] = ((unsigned long long)k << 32) |
                                 (unsigned long long)(0xFFFFFFFFu - n);
                }
            }
        }
    }
    __syncthreads();

    // ---- phase 3: bitonic sort 2048 desc (score desc, idx asc on ties) ----
    for (int k = 2; k <= 2048; k <<= 1)
        for (int j = k >> 1; j > 0; j >>= 1) {
            __syncthreads();
            for (int i = tid; i < 2048; i += 1024) {
                int ixj = i ^ j;
                if (ixj > i) {
                    unsigned long long a = arr[i], b = arr[ixj];
                    if (((i & k) == 0) ? (a < b) : (a > b)) { arr[i] = b; arr[ixj] = a; }
                }
            }
        }
    __syncthreads();

    // ---- epilogue: write topval + decode box inline ----
    if (tid < KK) {
        unsigned long long v = arr[tid];
        float val;
        int idx;
        if (v) {
            val = __uint_as_float((unsigned)(v >> 32));
            idx = (int)(0xFFFFFFFFu - (unsigned)v);
        } else {
            val = -1.0f;    // padding; cannot surface in output
            idx = tid;
        }
        g_topval[bc * KK + tid] = val;
        int b = bc / CC;
        float4 an = anchors[idx];
        float4 dl = deltas[(size_t)b * NN + idx];
        float acx = (an.x + an.z) * 0.5f, acy = (an.y + an.w) * 0.5f;
        float aw = fmaxf(an.z - an.x, 1.0f), ah = fmaxf(an.w - an.y, 1.0f);
        float cx = dl.x * aw + acx, cy = dl.y * ah + acy;
        float w = expf(fminf(dl.z, 4.0f)) * aw;
        float h = expf(fminf(dl.w, 4.0f)) * ah;
        g_topbox[bc * KK + tid] = make_float4(cx - w * 0.5f, cy - h * 0.5f,
                                              cx + w * 0.5f, cy + h * 0.5f);
    }
}

// ---------------- K3: NMS suppression bitmatrix (row-pair per warp, u32 words) ----------------
__global__ __launch_bounds__(1024) void nms_mask_kernel() {
    int bc = blockIdx.x;
    int tid = threadIdx.x;
    int lane = tid & 31;
    int wid = tid >> 5;
    __shared__ float4 sb[KK];
    __shared__ float sa[KK];
    for (int i = tid; i < KK; i += 1024) {
        float4 bx = g_topbox[bc * KK + i];
        sb[i] = bx;
        sa[i] = (bx.z - bx.x) * (bx.w - bx.y);
    }
    __syncthreads();
    int gw = blockIdx.y * 32 + wid;   // 0..127 global warp within bc
    for (int p = gw; p < KK / 2; p += 128) {
        int i0 = p * 2, i1 = i0 + 1;
        float4 bA = sb[i0], bB = sb[i1];
        float aA = sa[i0], aB = sa[i1];
        unsigned* r0 = &g_mask32[((size_t)bc * KK + i0) * 32];
        unsigned* r1 = r0 + 32;
        for (int w = i0 >> 5; w < 32; w++) {
            int j = (w << 5) + lane;
            bool sA = false, sB = false;
            if (j < KK) {
                float4 bj = sb[j];
                float aj = sa[j];
                float x1a = fmaxf(bA.x, bj.x), y1a = fmaxf(bA.y, bj.y);
                float x2a = fminf(bA.z, bj.z), y2a = fminf(bA.w, bj.w);
                float ia = fmaxf(x2a - x1a, 0.0f) * fmaxf(y2a - y1a, 0.0f);
                sA = (j > i0) && (ia > 0.5f * fmaxf(aA + aj - ia, 1e-6f));
                float x1b = fmaxf(bB.x, bj.x), y1b = fmaxf(bB.y, bj.y);
                float x2b = fminf(bB.z, bj.z), y2b = fminf(bB.w, bj.w);
                float ib = fmaxf(x2b - x1b, 0.0f) * fmaxf(y2b - y1b, 0.0f);
                sB = (j > i1) && (ib > 0.5f * fmaxf(aB + aj - ib, 1e-6f));
            }
            unsigned balA = __ballot_sync(0xFFFFFFFFu, sA);
            unsigned balB = __ballot_sync(0xFFFFFFFFu, sB);
            if (lane == 0) { r0[w] = balA; r1[w] = balB; }
        }
    }
}

// ---------------- K4: greedy reduction via 32x32 chunked triangle solve ----------------
// Lane l owns `removed` word l (bits l*32..l*32+31). For chunk c (rows c*32..c*32+31),
// lane c holds ALL diagonal words in its cur[] registers -> resolves the 32-row greedy
// sequence locally (no shfl in chain), then one shfl broadcasts the keep mask and all
// lanes apply suppression in parallel.
__global__ __launch_bounds__(32) void nms_reduce_kernel() {
    int bc = blockIdx.x;
    int lane = threadIdx.x;
    const unsigned* m32 = g_mask32 + (size_t)bc * KK * 32;
    unsigned removed = 0u;
    unsigned keepbits = 0u;
    unsigned cur[32], nxt[32];
#pragma unroll
    for (int s = 0; s < 32; s++) cur[s] = m32[(size_t)s * 32 + lane];

    for (int c = 0; c < 31; c++) {
        int basen = (c + 1) * 32;
#pragma unroll
        for (int s = 0; s < 32; s++)
            nxt[s] = (basen + s < KK) ? m32[(size_t)(basen + s) * 32 + lane] : 0u;
        // resolve (meaningful only on lane c, which holds the diagonal words)
        unsigned kb = ~removed;
#pragma unroll
        for (int s = 0; s < 32; s++) {
            unsigned m = (unsigned)(-(int)((kb >> s) & 1u));
            kb &= ~(cur[s] & m);
        }
        kb = __shfl_sync(0xFFFFFFFFu, kb, c);
        // apply kept rows' masks (4-way OR trees)
        unsigned a0 = 0, a1 = 0, a2 = 0, a3 = 0;
#pragma unroll
        for (int s = 0; s < 32; s += 4) {
            a0 |= cur[s + 0] & (unsigned)(-(int)((kb >> (s + 0)) & 1u));
            a1 |= cur[s + 1] & (unsigned)(-(int)((kb >> (s + 1)) & 1u));
            a2 |= cur[s + 2] & (unsigned)(-(int)((kb >> (s + 2)) & 1u));
            a3 |= cur[s + 3] & (unsigned)(-(int)((kb >> (s + 3)) & 1u));
        }
        removed |= (a0 | a1) | (a2 | a3);
        if (lane == c) keepbits = kb;
#pragma unroll
        for (int s = 0; s < 32; s++) cur[s] = nxt[s];
    }
    // tail chunk c=31: rows 992..999 in cur[0..7]
    {
        unsigned kb = ~removed & 0xFFu;
#pragma unroll
        for (int s = 0; s < 8; s++) {
            unsigned m = (unsigned)(-(int)((kb >> s) & 1u));
            kb &= ~(cur[s] & m);
        }
        kb = __shfl_sync(0xFFFFFFFFu, kb, 31);
        unsigned a0 = 0;
#pragma unroll
        for (int s = 0; s < 8; s++)
            a0 |= cur[s] & (unsigned)(-(int)((kb >> s) & 1u));
        removed |= a0;
        if (lane == 31) keepbits = kb;
    }

    // ---- parallel epilogue: apply score threshold, write g_val, compact survivors ----
    int cnt = 0;
    for (int w = 0; w < 32; w++) {
        unsigned kb = __shfl_sync(0xFFFFFFFFu, keepbits, w);
        int i = w * 32 + lane;
        float v = (i < KK) ? g_topval[bc * KK + i] : -1.0f;
        bool valid = (i < KK) && ((kb >> lane) & 1u) && (v > SCORE_T);
        if (i < KK) g_val[bc * KK + i] = valid ? v : 0.0f;
        unsigned bal = __ballot_sync(0xFFFFFFFFu, valid);
        int pos = cnt + __popc(bal & ((1u << lane) - 1u));
        if (valid) {
            g_cval[bc * KK + pos] = v;      // survivors stay score-descending
            g_cidx[bc * KK + pos] = i;
        }
        cnt += __popc(bal);
    }
    if (lane == 0) g_cnt[bc] = cnt;
}

// ---------------- K5: per-image top-100 over 9 classes ----------------
__global__ __launch_bounds__(512) void final_kernel(float* __restrict__ out) {
    int b = blockIdx.x;
    int tid = threadIdx.x;
    __shared__ unsigned long long arr[1024];
    for (int i = tid; i < 1024; i += 512) arr[i] = 0ull;
    __syncthreads();
    // only the top-100 of each class can reach the global top-100
    for (int s = tid; s < 900; s += 512) {
        int c = s / 100, r = s % 100;
        int bc = b * 9 + c;
        if (r < g_cnt[bc]) {
            float v = g_cval[bc * KK + r];
            int k = g_cidx[bc * KK + r];
            unsigned flat = (unsigned)(c * KK + k);
            arr[s] = ((unsigned long long)__float_as_uint(v) << 32) |
                     (unsigned long long)(0xFFFFFFFFu - flat);
        }
    }
    __syncthreads();
    for (int k = 2; k <= 1024; k <<= 1)
        for (int j = k >> 1; j > 0; j >>= 1) {
            __syncthreads();
            for (int i = tid; i < 1024; i += 512) {
                int ixj = i ^ j;
                if (ixj > i) {
                    unsigned long long a = arr[i], bv = arr[ixj];
                    if (((i & k) == 0) ? (a < bv) : (a > bv)) { arr[i] = bv; arr[ixj] = a; }
                }
            }
        }
    __syncthreads();

    float* o = out + (size_t)b * MAXDET * 6;
    if (tid < MAXDET) {
        unsigned long long v = arr[tid];
        if (v) {
            unsigned flat = 0xFFFFFFFFu - (unsigned)v;
            int c = flat / KK, k2 = flat % KK;
            float4 bx = g_topbox[(b * 9 + c) * KK + k2];
            float scv = __uint_as_float((unsigned)(v >> 32));
            o[tid * 6 + 0] = bx.x; o[tid * 6 + 1] = bx.y;
            o[tid * 6 + 2] = bx.z; o[tid * 6 + 3] = bx.w;
            o[tid * 6 + 4] = scv;  o[tid * 6 + 5] = (float)c;
        }
    }
    __syncthreads();
    // exact-tie fallback: < 100 positive detections -> zero-score entries by ascending flat idx
    if (tid == 0 && arr[MAXDET - 1] == 0ull) {
        int f = 0;
        for (int t = 0; t < MAXDET; t++) {
            if (arr[t]) continue;
            while (f < 9000 && g_val[(size_t)b * 9000 + f] != 0.0f) f++;
            int c = 0, k2 = 0;
            float4 bx = make_float4(0.f, 0.f, 0.f, 0.f);
            if (f < 9000) {
                c = f / KK; k2 = f % KK;
                bx = g_topbox[(b * 9 + c) * KK + k2];
                f++;
            }
            o[t * 6 + 0] = bx.x; o[t * 6 + 1] = bx.y;
            o[t * 6 + 2] = bx.z; o[t * 6 + 3] = bx.w;
            o[t * 6 + 4] = 0.0f; o[t * 6 + 5] = (float)c;
        }
    }
}

// ---------------- launch ----------------
extern "C" void kernel_launch(void* const* d_in, const int* in_sizes, int n_in,
                              void* d_out, int out_size) {
    (void)in_sizes; (void)n_in; (void)out_size;
    const float* anchors = (const float*)d_in[0];
    const float* deltas  = (const float*)d_in[1];
    const float* cls     = (const float*)d_in[2];
    const float* obj     = (const float*)d_in[3];
    float* out = (float*)d_out;

    score_kernel<<<dim3(NN / 256, BB), 256>>>(cls, obj);
    select_kernel<<<BC, 1024>>>((const float4*)anchors, (const float4*)deltas);
    nms_mask_kernel<<<dim3(BC, 4), 1024>>>();
    nms_reduce_kernel<<<BC, 32>>>();
    final_kernel<<<BB, 512>>>(out);
}

// round 7
// speedup vs baseline: 3.3168x; 1.0120x over previous
#include <cuda_runtime.h>
#include <cuda_bf16.h>
#include <cstdint>

#define NN 193536
#define BB 16
#define CC 9
#define KK 1000
#define BC 144            // BB*CC
#define MAXDET 100
#define SCORE_T 0.05f
#define IOU_T 0.5f

// keys are positive floats in (0.05, 1): 20-bit prefixes span [0x3D4CC, 0x3F7FF]
#define P_LO 0x3D4CCu
#define HB 9012
#define HBPAD 9024        // padded to 282*32
#define KT_MIN 0x3D4CCCCEu   // smallest uint key with float > 0.05f

// ---------------- scratch (static device globals; no dynamic alloc) ----------------
__device__ float    g_scores[(size_t)BC * NN];       // ~111.5 MB, [(b*9+c)][n]
__device__ float    g_topval[BC * KK];
__device__ float4   g_topbox[BC * KK];
__device__ unsigned g_mask32[(size_t)BC * KK * 32];  // 18.4 MB suppression bitmatrix (u32 words)
__device__ float    g_val[BC * KK];                  // post-NMS score (0 for invalid)
__device__ float    g_cval[BC * KK];                 // compacted survivors (desc order)
__device__ int      g_cidx[BC * KK];
__device__ int      g_cnt[BC];

// ---------------- K1: sigmoid + transpose scores to class-major ----------------
__global__ __launch_bounds__(256) void score_kernel(const float* __restrict__ cls,
                                                    const float* __restrict__ obj) {
    int b = blockIdx.y;
    int n0 = blockIdx.x * 256;
    int tid = threadIdx.x;
    __shared__ float sh[256 * 9];
    const float* src = cls + ((size_t)b * NN + n0) * 9;
    for (int i = tid; i < 2304; i += 256) sh[i] = src[i];
    __syncthreads();
    int n = n0 + tid;
    float so = 1.0f / (1.0f + expf(-obj[(size_t)b * NN + n]));
#pragma unroll
    for (int c = 0; c < 9; c++) {
        float s = 1.0f / (1.0f + expf(-sh[tid * 9 + c]));
        g_scores[((size_t)(b * 9 + c)) * NN + n] = s * so;
    }
}

// ---------------- scan helper: boundary bin from top, given remaining need ----------------
__device__ __forceinline__ void scan_boundary(unsigned* hist, unsigned* gsum, int NG,
                                              int tid, int* sh_sel, int* sh_need,
                                              int* sh_take, unsigned* sh_gat) {
    if (tid < NG) {
        unsigned t = 0;
        int base = tid * 32;
#pragma unroll 8
        for (int i = 0; i < 32; i++) t += hist[base + i];
        gsum[tid] = t;
    }
    __syncthreads();
    if (tid == 0) {
        int need = *sh_need;
        unsigned acc = 0;
        int g = NG - 1;
        for (; g >= 0; g--) {
            if (acc + gsum[g] >= (unsigned)need) break;
            acc += gsum[g];
        }
        if (g < 0) {
            *sh_take = 1;  // fewer than `need` candidates total
        } else {
            int bin = g * 32 + 31;
            for (;; bin--) {
                if (acc + hist[bin] >= (unsigned)need) break;
                acc += hist[bin];
            }
            *sh_sel = bin;
            *sh_need = need - (int)acc;          // remaining need inside boundary bin
            *sh_gat = acc + hist[bin];           // total items with key >= bin prefix
        }
    }
    __syncthreads();
}

// ---------------- K2: per-(b,c) exact top-1000 (sample-guided hist) + decode ----------------
__global__ __launch_bounds__(1024) void select_kernel(const float4* __restrict__ anchors,
                                                      const float4* __restrict__ deltas) {
    int bc = blockIdx.x;
    int tid = threadIdx.x;
    const float* sc = g_scores + (size_t)bc * NN;
    const float4* sc4 = (const float4*)sc;

    __shared__ __align__(16) unsigned char sraw[HBPAD * 4];   // 36 KB overlay
    unsigned* hist = (unsigned*)sraw;
    unsigned* samp = (unsigned*)sraw;                         // 8 KB sample buffer
    unsigned long long* arr = (unsigned long long*)sraw;      // 16 KB gather/sort buffer
    __shared__ unsigned gsum[288];
    __shared__ int sh_sel, sh_need, sh_take, sh_cnt;
    __shared__ unsigned sh_gat, sh_T;

    // ---- phase 0: sample 2048 values, sort desc, take 32nd as conservative threshold ----
    for (int i = tid; i < 2048; i += 1024) {
        float s = sc[i * 94];
        samp[i] = (s > SCORE_T) ? __float_as_uint(s) : 0u;
    }
    __syncthreads();
    for (int k = 2; k <= 2048; k <<= 1)
        for (int j = k >> 1; j > 0; j >>= 1) {
            __syncthreads();
            for (int i = tid; i < 2048; i += 1024) {
                int ixj = i ^ j;
                if (ixj > i) {
                    unsigned a = samp[i], b = samp[ixj];
                    if (((i & k) == 0) ? (a < b) : (a > b)) { samp[i] = b; samp[ixj] = a; }
                }
            }
        }
    __syncthreads();
    if (tid == 0) {
        unsigned t = samp[31];                 // 32nd largest sample (expected full rank ~3000)
        sh_T = (t >= KT_MIN) ? t : KT_MIN;
    }
    __syncthreads();
    unsigned T = sh_T;

    // ---- phase 1: histogram over 20-bit prefixes, only keys >= T (few atomics) ----
    for (int attempt = 0; attempt < 2; attempt++) {
        __syncthreads();
        for (int i = tid; i < HBPAD; i += 1024) hist[i] = 0;
        if (tid == 0) { sh_need = KK; sh_take = 0; }
        __syncthreads();
        for (int n4 = tid; n4 < NN / 4; n4 += 1024) {
            float4 v = sc4[n4];
            float sv[4] = {v.x, v.y, v.z, v.w};
#pragma unroll
            for (int c = 0; c < 4; c++) {
                float s = sv[c];
                if (s > SCORE_T) {
                    unsigned k = __float_as_uint(s);
                    if (k >= T) {
                        int bin = (int)(k >> 12) - (int)P_LO;
                        bin = min(max(bin, 0), HB - 1);
                        atomicAdd(&hist[bin], 1u);
                    }
                }
            }
        }
        __syncthreads();
        scan_boundary(hist, gsum, 282, tid, &sh_sel, &sh_need, &sh_take, &sh_gat);
        if (!sh_take || T == KT_MIN) break;    // success, or genuinely <1000 total
        T = KT_MIN;                            // sample threshold too high: full rehist
    }

    unsigned Kt;
    if (sh_take) {
        Kt = KT_MIN;                           // fewer than 1000 total: take everything > thresh
    } else {
        unsigned prefix = P_LO + (unsigned)sh_sel;
        unsigned binlo = prefix << 12;
        Kt = (binlo < T) ? T : binlo;          // boundary bin may be T's own bin
        if (sh_gat > 2048u) {
            // ---- rare refinement: low 12 bits within boundary prefix (exact key bins) ----
            __syncthreads();
            for (int i = tid; i < 4096; i += 1024) hist[i] = 0;
            __syncthreads();
            for (int n4 = tid; n4 < NN / 4; n4 += 1024) {
                float4 v = sc4[n4];
                float sv[4] = {v.x, v.y, v.z, v.w};
#pragma unroll
                for (int c = 0; c < 4; c++) {
                    float s = sv[c];
                    if (s > SCORE_T) {
                        unsigned k = __float_as_uint(s);
                        if (k >= T && (k >> 12) == prefix) atomicAdd(&hist[k & 0xFFF], 1u);
                    }
                }
            }
            __syncthreads();
            scan_boundary(hist, gsum, 128, tid, &sh_sel, &sh_need, &sh_take, &sh_gat);
            Kt = (prefix << 12) | (unsigned)sh_sel;   // exact 32-bit threshold (>= T)
        }
    }

    // ---- phase 2: gather candidates with key >= Kt ----
    __syncthreads();
    for (int i = tid; i < 2048; i += 1024) arr[i] = 0ull;
    if (tid == 0) sh_cnt = 0;
    __syncthreads();
    for (int n4 = tid; n4 < NN / 4; n4 += 1024) {
        float4 v = sc4[n4];
        float sv[4] = {v.x, v.y, v.z, v.w};
#pragma unroll
        for (int c = 0; c < 4; c++) {
            float s = sv[c];
            if (s > SCORE_T) {
                unsigned k = __float_as_uint(s);
                if (k >= Kt) {
                    int p = atomicAdd(&sh_cnt, 1);
                    unsigned n = (unsigned)(n4 * 4 + c);
                    if (p < 2048)
                        arr[p] = ((unsigned long long)k << 32) |
                                 (unsigned long long)(0xFFFFFFFFu - n);
                }
            }
        }
    }
    __syncthreads();

    // ---- phase 3: bitonic sort 2048 desc (score desc, idx asc on ties) ----
    for (int k = 2; k <= 2048; k <<= 1)
        for (int j = k >> 1; j > 0; j >>= 1) {
            __syncthreads();
            for (int i = tid; i < 2048; i += 1024) {
                int ixj = i ^ j;
                if (ixj > i) {
                    unsigned long long a = arr[i], b = arr[ixj];
                    if (((i & k) == 0) ? (a < b) : (a > b)) { arr[i] = b; arr[ixj] = a; }
                }
            }
        }
    __syncthreads();

    // ---- epilogue: write topval + decode box inline ----
    if (tid < KK) {
        unsigned long long v = arr[tid];
        float val;
        int idx;
        if (v) {
            val = __uint_as_float((unsigned)(v >> 32));
            idx = (int)(0xFFFFFFFFu - (unsigned)v);
        } else {
            val = -1.0f;    // padding; cannot surface in output
            idx = tid;
        }
        g_topval[bc * KK + tid] = val;
        int b = bc / CC;
        float4 an = anchors[idx];
        float4 dl = deltas[(size_t)b * NN + idx];
        float acx = (an.x + an.z) * 0.5f, acy = (an.y + an.w) * 0.5f;
        float aw = fmaxf(an.z - an.x, 1.0f), ah = fmaxf(an.w - an.y, 1.0f);
        float cx = dl.x * aw + acx, cy = dl.y * ah + acy;
        float w = expf(fminf(dl.z, 4.0f)) * aw;
        float h = expf(fminf(dl.w, 4.0f)) * ah;
        g_topbox[bc * KK + tid] = make_float4(cx - w * 0.5f, cy - h * 0.5f,
                                              cx + w * 0.5f, cy + h * 0.5f);
    }
}

// ---------------- K3: NMS suppression bitmatrix (row-pair per warp, u32 words) ----------------
__global__ __launch_bounds__(1024) void nms_mask_kernel() {
    int bc = blockIdx.x;
    int tid = threadIdx.x;
    int lane = tid & 31;
    int wid = tid >> 5;
    __shared__ float4 sb[KK];
    __shared__ float sa[KK];
    for (int i = tid; i < KK; i += 1024) {
        float4 bx = g_topbox[bc * KK + i];
        sb[i] = bx;
        sa[i] = (bx.z - bx.x) * (bx.w - bx.y);
    }
    __syncthreads();
    int gw = blockIdx.y * 32 + wid;   // 0..127 global warp within bc
    for (int p = gw; p < KK / 2; p += 128) {
        int i0 = p * 2, i1 = i0 + 1;
        float4 bA = sb[i0], bB = sb[i1];
        float aA = sa[i0], aB = sa[i1];
        unsigned* r0 = &g_mask32[((size_t)bc * KK + i0) * 32];
        unsigned* r1 = r0 + 32;
        for (int w = i0 >> 5; w < 32; w++) {
            int j = (w << 5) + lane;
            bool sA = false, sB = false;
            if (j < KK) {
                float4 bj = sb[j];
                float aj = sa[j];
                float x1a = fmaxf(bA.x, bj.x), y1a = fmaxf(bA.y, bj.y);
                float x2a = fminf(bA.z, bj.z), y2a = fminf(bA.w, bj.w);
                float ia = fmaxf(x2a - x1a, 0.0f) * fmaxf(y2a - y1a, 0.0f);
                sA = (j > i0) && (ia > 0.5f * fmaxf(aA + aj - ia, 1e-6f));
                float x1b = fmaxf(bB.x, bj.x), y1b = fmaxf(bB.y, bj.y);
                float x2b = fminf(bB.z, bj.z), y2b = fminf(bB.w, bj.w);
                float ib = fmaxf(x2b - x1b, 0.0f) * fmaxf(y2b - y1b, 0.0f);
                sB = (j > i1) && (ib > 0.5f * fmaxf(aB + aj - ib, 1e-6f));
            }
            unsigned balA = __ballot_sync(0xFFFFFFFFu, sA);
            unsigned balB = __ballot_sync(0xFFFFFFFFu, sB);
            if (lane == 0) { r0[w] = balA; r1[w] = balB; }
        }
    }
}

// ---------------- K4: greedy reduction via 32x32 chunked triangle solve ----------------
// Lane l owns `removed` word l (bits l*32..l*32+31). For chunk c (rows c*32..c*32+31),
// lane c holds ALL diagonal words in its cur[] registers -> resolves the 32-row greedy
// sequence locally (no shfl in chain), then one shfl broadcasts the keep mask and all
// lanes apply suppression in parallel.
__global__ __launch_bounds__(32) void nms_reduce_kernel() {
    int bc = blockIdx.x;
    int lane = threadIdx.x;
    const unsigned* m32 = g_mask32 + (size_t)bc * KK * 32;
    unsigned removed = 0u;
    unsigned keepbits = 0u;
    unsigned cur[32], nxt[32];
#pragma unroll
    for (int s = 0; s < 32; s++) cur[s] = m32[(size_t)s * 32 + lane];

    for (int c = 0; c < 31; c++) {
        int basen = (c + 1) * 32;
#pragma unroll
        for (int s = 0; s < 32; s++)
            nxt[s] = (basen + s < KK) ? m32[(size_t)(basen + s) * 32 + lane] : 0u;
        // resolve (meaningful only on lane c, which holds the diagonal words)
        unsigned kb = ~removed;
#pragma unroll
        for (int s = 0; s < 32; s++) {
            unsigned m = (unsigned)(-(int)((kb >> s) & 1u));
            kb &= ~(cur[s] & m);
        }
        kb = __shfl_sync(0xFFFFFFFFu, kb, c);
        // apply kept rows' masks (4-way OR trees)
        unsigned a0 = 0, a1 = 0, a2 = 0, a3 = 0;
#pragma unroll
        for (int s = 0; s < 32; s += 4) {
            a0 |= cur[s + 0] & (unsigned)(-(int)((kb >> (s + 0)) & 1u));
            a1 |= cur[s + 1] & (unsigned)(-(int)((kb >> (s + 1)) & 1u));
            a2 |= cur[s + 2] & (unsigned)(-(int)((kb >> (s + 2)) & 1u));
            a3 |= cur[s + 3] & (unsigned)(-(int)((kb >> (s + 3)) & 1u));
        }
        removed |= (a0 | a1) | (a2 | a3);
        if (lane == c) keepbits = kb;
#pragma unroll
        for (int s = 0; s < 32; s++) cur[s] = nxt[s];
    }
    // tail chunk c=31: rows 992..999 in cur[0..7]
    {
        unsigned kb = ~removed & 0xFFu;
#pragma unroll
        for (int s = 0; s < 8; s++) {
            unsigned m = (unsigned)(-(int)((kb >> s) & 1u));
            kb &= ~(cur[s] & m);
        }
        kb = __shfl_sync(0xFFFFFFFFu, kb, 31);
        unsigned a0 = 0;
#pragma unroll
        for (int s = 0; s < 8; s++)
            a0 |= cur[s] & (unsigned)(-(int)((kb >> s) & 1u));
        removed |= a0;
        if (lane == 31) keepbits = kb;
    }

    // ---- parallel epilogue: apply score threshold, write g_val, compact survivors ----
    int cnt = 0;
    for (int w = 0; w < 32; w++) {
        unsigned kb = __shfl_sync(0xFFFFFFFFu, keepbits, w);
        int i = w * 32 + lane;
        float v = (i < KK) ? g_topval[bc * KK + i] : -1.0f;
        bool valid = (i < KK) && ((kb >> lane) & 1u) && (v > SCORE_T);
        if (i < KK) g_val[bc * KK + i] = valid ? v : 0.0f;
        unsigned bal = __ballot_sync(0xFFFFFFFFu, valid);
        int pos = cnt + __popc(bal & ((1u << lane) - 1u));
        if (valid) {
            g_cval[bc * KK + pos] = v;      // survivors stay score-descending
            g_cidx[bc * KK + pos] = i;
        }
        cnt += __popc(bal);
    }
    if (lane == 0) g_cnt[bc] = cnt;
}

// ---------------- K5: per-image top-100 over 9 classes ----------------
__global__ __launch_bounds__(512) void final_kernel(float* __restrict__ out) {
    int b = blockIdx.x;
    int tid = threadIdx.x;
    __shared__ unsigned long long arr[1024];
    for (int i = tid; i < 1024; i += 512) arr[i] = 0ull;
    __syncthreads();
    // only the top-100 of each class can reach the global top-100
    for (int s = tid; s < 900; s += 512) {
        int c = s / 100, r = s % 100;
        int bc = b * 9 + c;
        if (r < g_cnt[bc]) {
            float v = g_cval[bc * KK + r];
            int k = g_cidx[bc * KK + r];
            unsigned flat = (unsigned)(c * KK + k);
            arr[s] = ((unsigned long long)__float_as_uint(v) << 32) |
                     (unsigned long long)(0xFFFFFFFFu - flat);
        }
    }
    __syncthreads();
    for (int k = 2; k <= 1024; k <<= 1)
        for (int j = k >> 1; j > 0; j >>= 1) {
            __syncthreads();
            for (int i = tid; i < 1024; i += 512) {
                int ixj = i ^ j;
                if (ixj > i) {
                    unsigned long long a = arr[i], bv = arr[ixj];
                    if (((i & k) == 0) ? (a < bv) : (a > bv)) { arr[i] = bv; arr[ixj] = a; }
                }
            }
        }
    __syncthreads();

    float* o = out + (size_t)b * MAXDET * 6;
    if (tid < MAXDET) {
        unsigned long long v = arr[tid];
        if (v) {
            unsigned flat = 0xFFFFFFFFu - (unsigned)v;
            int c = flat / KK, k2 = flat % KK;
            float4 bx = g_topbox[(b * 9 + c) * KK + k2];
            float scv = __uint_as_float((unsigned)(v >> 32));
            o[tid * 6 + 0] = bx.x; o[tid * 6 + 1] = bx.y;
            o[tid * 6 + 2] = bx.z; o[tid * 6 + 3] = bx.w;
            o[tid * 6 + 4] = scv;  o[tid * 6 + 5] = (float)c;
        }
    }
    __syncthreads();
    // exact-tie fallback: < 100 positive detections -> zero-score entries by ascending flat idx
    if (tid == 0 && arr[MAXDET - 1] == 0ull) {
        int f = 0;
        for (int t = 0; t < MAXDET; t++) {
            if (arr[t]) continue;
            while (f < 9000 && g_val[(size_t)b * 9000 + f] != 0.0f) f++;
            int c = 0, k2 = 0;
            float4 bx = make_float4(0.f, 0.f, 0.f, 0.f);
            if (f < 9000) {
                c = f / KK; k2 = f % KK;
                bx = g_topbox[(b * 9 + c) * KK + k2];
                f++;
            }
            o[t * 6 + 0] = bx.x; o[t * 6 + 1] = bx.y;
            o[t * 6 + 2] = bx.z; o[t * 6 + 3] = bx.w;
            o[t * 6 + 4] = 0.0f; o[t * 6 + 5] = (float)c;
        }
    }
}

// ---------------- launch ----------------
extern "C" void kernel_launch(void* const* d_in, const int* in_sizes, int n_in,
                              void* d_out, int out_size) {
    (void)in_sizes; (void)n_in; (void)out_size;
    const float* anchors = (const float*)d_in[0];
    const float* deltas  = (const float*)d_in[1];
    const float* cls     = (const float*)d_in[2];
    const float* obj     = (const float*)d_in[3];
    float* out = (float*)d_out;

    score_kernel<<<dim3(NN / 256, BB), 256>>>(cls, obj);
    select_kernel<<<BC, 1024>>>((const float4*)anchors, (const float4*)deltas);
    nms_mask_kernel<<<dim3(BC, 4), 1024>>>();
    nms_reduce_kernel<<<BC, 32>>>();
    final_kernel<<<BB, 512>>>(out);
}